// round 12
// baseline (speedup 1.0000x reference)
#include <cuda_runtime.h>
#include <cuda_fp16.h>
#include <cstdint>
#include <math.h>

#define NTOK 4096
#define HDIM 4096
#define FDIM 14336
#define NEXP 8
#define NR   8
#define LSCALE 2.0f

#define TR_BLOCKS (3 * 28672)

// ---------------------------------------------------------------------------
// Scratch (__device__ globals; allocation-free rule)
// ---------------------------------------------------------------------------
__device__ __half g_xh[(size_t)NTOK * HDIM];   // x as fp16 [N,H]
__device__ __half g_b1[(size_t)FDIM * HDIM];   // w1^T [F,H] fp16
__device__ __half g_b3[(size_t)FDIM * HDIM];   // w3^T [F,H] fp16
__device__ __half g_b2[(size_t)HDIM * FDIM];   // w2^T [H,F] fp16
__device__ __half g_a2[(size_t)NTOK * FDIM];   // silu(gate)*up fp16 [N,F]
__device__ float  g_c[NTOK * NEXP * NR];       // LoRA coefficients

// ---------------------------------------------------------------------------
// Asm helpers (sm_80-level features; legal on plain sm_103 target)
// ---------------------------------------------------------------------------
__device__ __forceinline__ uint32_t smem_u32(const void* p) {
    uint32_t a;
    asm("{ .reg .u64 t; cvta.to.shared.u64 t, %1; cvt.u32.u64 %0, t; }" : "=r"(a) : "l"(p));
    return a;
}

#define CP16(dst, src) \
    asm volatile("cp.async.cg.shared.global [%0], [%1], 16;" :: "r"(dst), "l"(src))
#define CP_COMMIT() asm volatile("cp.async.commit_group;" ::: "memory")
#define CP_WAIT1()  asm volatile("cp.async.wait_group 1;" ::: "memory")

#define LDSM4(r0, r1, r2, r3, a) \
    asm volatile("ldmatrix.sync.aligned.m8n8.x4.shared.b16 {%0,%1,%2,%3}, [%4];" \
        : "=r"(r0), "=r"(r1), "=r"(r2), "=r"(r3) : "r"(a))

#define MMA_F16(c, a0, a1, a2, a3, b0, b1) \
    asm volatile("mma.sync.aligned.m16n8k16.row.col.f32.f16.f16.f32 " \
        "{%0,%1,%2,%3}, {%4,%5,%6,%7}, {%8,%9}, {%0,%1,%2,%3};" \
        : "+f"((c)[0]), "+f"((c)[1]), "+f"((c)[2]), "+f"((c)[3]) \
        : "r"(a0), "r"(a1), "r"(a2), "r"(a3), "r"(b0), "r"(b1))

// ---------------------------------------------------------------------------
// MERGED prep kernel: 1D grid.
//   bid < TR_BLOCKS  : weight transpose (w1 / w3 / w2 by range)
//   else             : router + LoRA coeffs + x fp16 conversion (token = bid-TR_BLOCKS)
// Shared memory is a union: transpose needs 8.5KB, router needs 24.6KB.
// ---------------------------------------------------------------------------
#define PREP_SMEM_BYTES ((HDIM + 8 * 32 * NR + 16) * 4)   // 24640 B

__global__ void __launch_bounds__(256) prep_kernel(
    const float* __restrict__ x, const float* __restrict__ router_w,
    const float* __restrict__ lora_A, float* __restrict__ logits_out,
    const float* __restrict__ w1, const float* __restrict__ w3,
    const float* __restrict__ w2,
    __half* __restrict__ b1, __half* __restrict__ b3, __half* __restrict__ b2)
{
    __shared__ __align__(16) char smraw[PREP_SMEM_BYTES];
    int bid = blockIdx.x;
    int tid = threadIdx.x;

    if (bid < TR_BLOCKS) {
        // ---------------- transpose path ----------------
        float (*t)[33] = reinterpret_cast<float(*)[33]>(smraw);
        int which = bid / 28672;
        int b     = bid % 28672;
        const float* W;
        __half* out;
        int K, N, nBlk;
        if (which == 0)      { W = w1; out = b1; K = HDIM; N = FDIM; nBlk = FDIM / 32; }
        else if (which == 1) { W = w3; out = b3; K = HDIM; N = FDIM; nBlk = FDIM / 32; }
        else                 { W = w2; out = b2; K = FDIM; N = HDIM; nBlk = HDIM / 32; }

        int n0 = (b % nBlk) * 32;
        int k0 = (b / nBlk) * 64;
        int tx = tid & 31, ty = tid >> 5;   // 32 x 8
        #pragma unroll
        for (int j = 0; j < 8; j++)
            t[ty + 8 * j][tx] = W[(size_t)(k0 + ty + 8 * j) * N + n0 + tx];
        __syncthreads();
        #pragma unroll
        for (int j = 0; j < 4; j++) {
            int n = ty + 8 * j;
            __half2 h = __floats2half2_rn(t[2 * tx][n], t[2 * tx + 1][n]);
            *(__half2*)(out + (size_t)(n0 + n) * K + k0 + 2 * tx) = h;
        }
        return;
    }

    // ---------------- router path (256 threads) ----------------
    int n = bid - TR_BLOCKS;
    float* xs = (float*)smraw;                                   // HDIM floats
    float (*red)[32][NR] = (float(*)[32][NR])(smraw + HDIM * 4); // 8 warps
    float* logits = (float*)(smraw + HDIM * 4 + 8 * 32 * NR * 4);
    int*   sel    = (int*)(logits + NEXP);
    float* rws    = (float*)(sel + 2);

    const float* xr = x + (size_t)n * HDIM;
    for (int i = tid; i < HDIM / 4; i += 256)
        ((float4*)xs)[i] = ((const float4*)xr)[i];
    __syncthreads();

    // fp16 conversion of x
    {
        __half* xo = g_xh + (size_t)n * HDIM;
        for (int i = tid; i < HDIM / 2; i += 256)
            *(__half2*)(xo + 2 * i) = __floats2half2_rn(xs[2 * i], xs[2 * i + 1]);
    }

    int wid = tid >> 5, lane = tid & 31;
    // logits: one expert per warp
    {
        int e = wid;
        const float* wr = router_w + (size_t)e * HDIM;
        float s = 0.f;
        for (int h = lane; h < HDIM; h += 32) s += xs[h] * wr[h];
        #pragma unroll
        for (int o = 16; o; o >>= 1) s += __shfl_down_sync(0xffffffffu, s, o);
        if (lane == 0) {
            logits[e] = s;
            if (logits_out) logits_out[(size_t)n * NEXP + e] = s;
        }
    }
    __syncthreads();

    if (tid == 0) {
        float m = -1e30f;
        for (int e = 0; e < NEXP; e++) m = fmaxf(m, logits[e]);
        float p[NEXP];
        for (int e = 0; e < NEXP; e++) p[e] = expf(logits[e] - m);
        int i0 = 0;
        for (int e = 1; e < NEXP; e++) if (p[e] > p[i0]) i0 = e;
        int i1 = -1;
        for (int e = 0; e < NEXP; e++) {
            if (e == i0) continue;
            if (i1 < 0 || p[e] > p[i1]) i1 = e;
        }
        float s2 = p[i0] + p[i1];
        sel[0] = i0; sel[1] = i1;
        rws[0] = p[i0] / s2; rws[1] = p[i1] / s2;
    }
    if (tid < NEXP * NR) g_c[n * NEXP * NR + tid] = 0.f;
    __syncthreads();

    // coalesced LoRA-A projection: warp -> (expert slot k = wid>>2, h-quarter)
    {
        int k = wid >> 2;                       // 0..1
        int q = wid & 3;                        // 0..3
        int e = sel[k];
        const float* A = lora_A + (size_t)e * HDIM * NR;
        float acc[NR];
        #pragma unroll
        for (int r = 0; r < NR; r++) acc[r] = 0.f;
        int h0 = q * (HDIM / 4);
        for (int it = 0; it < (HDIM / 4) / 32; it++) {
            int h = h0 + it * 32 + lane;
            const float4* ap = (const float4*)(A + (size_t)h * NR);
            float4 a0 = ap[0];
            float4 a1 = ap[1];
            float xv = xs[h];
            acc[0] += xv * a0.x; acc[1] += xv * a0.y;
            acc[2] += xv * a0.z; acc[3] += xv * a0.w;
            acc[4] += xv * a1.x; acc[5] += xv * a1.y;
            acc[6] += xv * a1.z; acc[7] += xv * a1.w;
        }
        #pragma unroll
        for (int r = 0; r < NR; r++) red[wid][lane][r] = acc[r];
    }
    __syncthreads();

    if (tid < 2 * NR) {
        int k = tid >> 3;
        int r = tid & 7;
        float s = 0.f;
        #pragma unroll
        for (int w = 0; w < 4; w++)
            for (int l = 0; l < 32; l++)
                s += red[4 * k + w][l][r];
        g_c[n * NEXP * NR + sel[k] * NR + r] = rws[k] * LSCALE * s;
    }
}

// ---------------------------------------------------------------------------
// Small fp32 SGEMM for LoRA (K=64), writes out with beta=0
// ---------------------------------------------------------------------------
__global__ void __launch_bounds__(256) sgemm128_kernel(
    const float* __restrict__ A, const float* __restrict__ B,
    float* __restrict__ C, int M, int N, int K)
{
    __shared__ float As[8][128];
    __shared__ float Bs[8][128];
    int tid = threadIdx.x;
    int m0 = blockIdx.y * 128, n0 = blockIdx.x * 128;
    int aRow = tid >> 1, aCol = (tid & 1) * 4;
    int bRow = tid >> 5, bCol = (tid & 31) * 4;
    const float* Aptr = A + (size_t)(m0 + aRow) * K + aCol;
    const float* Bptr = B + (size_t)bRow * N + n0 + bCol;
    int ty = tid >> 4, tx = tid & 15;

    float acc[8][8];
    #pragma unroll
    for (int i = 0; i < 8; i++)
        #pragma unroll
        for (int j = 0; j < 8; j++) acc[i][j] = 0.f;

    for (int k0 = 0; k0 < K; k0 += 8) {
        float4 av = *(const float4*)Aptr; Aptr += 8;
        float4 bv = *(const float4*)Bptr; Bptr += (size_t)8 * N;
        As[aCol + 0][aRow] = av.x; As[aCol + 1][aRow] = av.y;
        As[aCol + 2][aRow] = av.z; As[aCol + 3][aRow] = av.w;
        *(float4*)&Bs[bRow][bCol] = bv;
        __syncthreads();
        #pragma unroll
        for (int kk = 0; kk < 8; kk++) {
            float a[8], b[8];
            *(float4*)(a)     = *(const float4*)&As[kk][ty * 8];
            *(float4*)(a + 4) = *(const float4*)&As[kk][ty * 8 + 4];
            *(float4*)(b)     = *(const float4*)&Bs[kk][tx * 8];
            *(float4*)(b + 4) = *(const float4*)&Bs[kk][tx * 8 + 4];
            #pragma unroll
            for (int i = 0; i < 8; i++)
                #pragma unroll
                for (int j = 0; j < 8; j++)
                    acc[i][j] = fmaf(a[i], b[j], acc[i][j]);
        }
        __syncthreads();
    }
    #pragma unroll
    for (int i = 0; i < 8; i++) {
        float* Cr = C + (size_t)(m0 + ty * 8 + i) * N + n0 + tx * 8;
        *(float4*)Cr       = make_float4(acc[i][0], acc[i][1], acc[i][2], acc[i][3]);
        *(float4*)(Cr + 4) = make_float4(acc[i][4], acc[i][5], acc[i][6], acc[i][7]);
    }
}

// ---------------------------------------------------------------------------
// FUSED gate+up GEMM, 128m x 64n CTA tile (occ=2).
// ---------------------------------------------------------------------------
#define FSTG 32768
#define FUSED_SMEM (3 * FSTG)

__device__ __forceinline__ void issue_stage_gu(
    uint32_t st, const __half* A, const __half* B1, const __half* B3,
    int m0, int n0, int kpos, int K, int lr, int lkc)
{
    #pragma unroll
    for (int rr = 0; rr < 256; rr += 32) {
        int row = lr + rr;
        uint32_t so = row * 128 + ((lkc ^ (row & 7)) << 4);
        const __half* src;
        if (rr < 128)      src = A  + (size_t)(m0 + row) * K;
        else if (rr < 192) src = B1 + (size_t)(n0 + row - 128) * K;
        else               src = B3 + (size_t)(n0 + row - 192) * K;
        CP16(st + so, src + kpos + lkc * 8);
    }
    CP_COMMIT();
}

__global__ void __launch_bounds__(256, 2) gemm_gateup_kernel(
    const __half* __restrict__ A, const __half* __restrict__ B1,
    const __half* __restrict__ B3, __half* __restrict__ oA2, int K)
{
    extern __shared__ __align__(1024) char smem[];
    uint32_t sb = smem_u32(smem);
    int tid = threadIdx.x;
    int wid = tid >> 5, lane = tid & 31;
    int wm = wid >> 2, wn = wid & 3;

    int lin = blockIdx.y * gridDim.x + blockIdx.x;
    int gs  = 8 * gridDim.y;
    int g   = lin / gs, r = lin - g * gs;
    int m0  = (r >> 3) * 128;
    int n0  = (g * 8 + (r & 7)) * 64;

    int NT = K >> 6;
    int lr = tid >> 3, lkc = tid & 7;

    int laneM  = lane & 15;
    int kHalfA = lane >> 4;
    int aSw    = laneM & 7;
    uint32_t rowOffA[4];
    #pragma unroll
    for (int tm = 0; tm < 4; tm++)
        rowOffA[tm] = (uint32_t)(wm * 64 + tm * 16 + laneM) * 128;
    int l7     = lane & 7;
    int kHalfB = (lane >> 3) & 1;
    uint32_t rowB = (uint32_t)(wn * 16 + ((lane >> 4) & 1) * 8 + l7) * 128;

    float accG[4][2][4], accU[4][2][4];
    #pragma unroll
    for (int i = 0; i < 4; i++)
        #pragma unroll
        for (int j = 0; j < 2; j++)
            #pragma unroll
            for (int q = 0; q < 4; q++) { accG[i][j][q] = 0.f; accU[i][j][q] = 0.f; }

    issue_stage_gu(sb,        A, B1, B3, m0, n0, 0,  K, lr, lkc);
    issue_stage_gu(sb + FSTG, A, B1, B3, m0, n0, 64, K, lr, lkc);

    for (int kt = 0; kt < NT; kt++) {
        CP_WAIT1();
        __syncthreads();
        if (kt + 2 < NT)
            issue_stage_gu(sb + ((kt + 2) % 3) * FSTG, A, B1, B3,
                           m0, n0, (kt + 2) << 6, K, lr, lkc);
        else
            CP_COMMIT();

        uint32_t st = sb + (kt % 3) * FSTG;
        #pragma unroll
        for (int kk = 0; kk < 4; kk++) {
            uint32_t ah[4][4], b1f[4], b3f[4];
            uint32_t chA = (uint32_t)(((kk * 2 + kHalfA) ^ aSw) << 4);
            #pragma unroll
            for (int tm = 0; tm < 4; tm++)
                LDSM4(ah[tm][0], ah[tm][1], ah[tm][2], ah[tm][3], st + rowOffA[tm] + chA);
            uint32_t chB = (uint32_t)(((kk * 2 + kHalfB) ^ l7) << 4);
            LDSM4(b1f[0], b1f[1], b1f[2], b1f[3], st + 16384 + rowB + chB);
            LDSM4(b3f[0], b3f[1], b3f[2], b3f[3], st + 24576 + rowB + chB);
            #pragma unroll
            for (int tm = 0; tm < 4; tm++)
                #pragma unroll
                for (int tn = 0; tn < 2; tn++) {
                    MMA_F16(accG[tm][tn], ah[tm][0], ah[tm][1], ah[tm][2], ah[tm][3],
                            b1f[2 * tn], b1f[2 * tn + 1]);
                    MMA_F16(accU[tm][tn], ah[tm][0], ah[tm][1], ah[tm][2], ah[tm][3],
                            b3f[2 * tn], b3f[2 * tn + 1]);
                }
        }
    }

    int g2 = lane >> 2, q2 = (lane & 3) * 2;
    size_t Nt = (size_t)gridDim.x * 64;
    #pragma unroll
    for (int tm = 0; tm < 4; tm++) {
        #pragma unroll
        for (int tn = 0; tn < 2; tn++) {
            int mg = m0 + wm * 64 + tm * 16 + g2;
            int cg = n0 + wn * 16 + tn * 8 + q2;
            size_t o0 = (size_t)mg * Nt + cg;
            size_t o1 = o0 + 8 * Nt;
            float* gg = accG[tm][tn];
            float* uu = accU[tm][tn];
            float v0 = gg[0] / (1.f + __expf(-gg[0])) * uu[0];
            float v1 = gg[1] / (1.f + __expf(-gg[1])) * uu[1];
            float v2 = gg[2] / (1.f + __expf(-gg[2])) * uu[2];
            float v3 = gg[3] / (1.f + __expf(-gg[3])) * uu[3];
            *(__half2*)(oA2 + o0) = __floats2half2_rn(v0, v1);
            *(__half2*)(oA2 + o1) = __floats2half2_rn(v2, v3);
        }
    }
}

// ---------------------------------------------------------------------------
// Down-projection fp16 GEMM (accumulate onto out): C += A @ B^T
// 128x128 tile, occ=2, raster swizzle.
// ---------------------------------------------------------------------------
#define STAGE_BYTES 32768
#define GEMM_SMEM   (3 * STAGE_BYTES)

__device__ __forceinline__ void issue_stage_f16(
    uint32_t st, const __half* A, const __half* B,
    int m0, int n0, int kpos, int K, int lr, int lkc)
{
    #pragma unroll
    for (int rr = 0; rr < 128; rr += 32) {
        int row = lr + rr;
        uint32_t so = row * 128 + ((lkc ^ (row & 7)) << 4);
        size_t ga = (size_t)(m0 + row) * K + kpos + lkc * 8;
        size_t gb = (size_t)(n0 + row) * K + kpos + lkc * 8;
        CP16(st + so,         A + ga);
        CP16(st + 16384 + so, B + gb);
    }
    CP_COMMIT();
}

__global__ void __launch_bounds__(256, 2) gemm_down_kernel(
    const __half* __restrict__ A, const __half* __restrict__ B,
    float* __restrict__ C, int K)
{
    extern __shared__ __align__(1024) char smem[];
    uint32_t sb = smem_u32(smem);
    int tid = threadIdx.x;
    int wid = tid >> 5, lane = tid & 31;
    int wm = wid >> 2, wn = wid & 3;

    int lin = blockIdx.y * gridDim.x + blockIdx.x;
    int gs  = 8 * gridDim.y;
    int g   = lin / gs, r = lin - g * gs;
    int m0  = (r >> 3) * 128;
    int n0  = (g * 8 + (r & 7)) * 128;

    int NT = K >> 6;
    int lr = tid >> 3, lkc = tid & 7;

    int laneM  = lane & 15;
    int kHalfA = lane >> 4;
    int aSw    = laneM & 7;
    uint32_t rowOffA[4];
    #pragma unroll
    for (int tm = 0; tm < 4; tm++)
        rowOffA[tm] = (uint32_t)(wm * 64 + tm * 16 + laneM) * 128;
    int l7     = lane & 7;
    int kHalfB = (lane >> 3) & 1;
    uint32_t rowOffB[2];
    #pragma unroll
    for (int pr = 0; pr < 2; pr++)
        rowOffB[pr] = (uint32_t)(wn * 32 + pr * 16 + ((lane >> 4) & 1) * 8 + l7) * 128;

    float acc[4][4][4];
    #pragma unroll
    for (int i = 0; i < 4; i++)
        #pragma unroll
        for (int j = 0; j < 4; j++)
            #pragma unroll
            for (int q = 0; q < 4; q++) acc[i][j][q] = 0.f;

    issue_stage_f16(sb,               A, B, m0, n0, 0,  K, lr, lkc);
    issue_stage_f16(sb + STAGE_BYTES, A, B, m0, n0, 64, K, lr, lkc);

    for (int kt = 0; kt < NT; kt++) {
        CP_WAIT1();
        __syncthreads();
        if (kt + 2 < NT)
            issue_stage_f16(sb + ((kt + 2) % 3) * STAGE_BYTES, A, B,
                            m0, n0, (kt + 2) << 6, K, lr, lkc);
        else
            CP_COMMIT();

        uint32_t st = sb + (kt % 3) * STAGE_BYTES;
        #pragma unroll
        for (int kk = 0; kk < 4; kk++) {
            uint32_t ah[4][4], bh[8];
            uint32_t chA = (uint32_t)(((kk * 2 + kHalfA) ^ aSw) << 4);
            #pragma unroll
            for (int tm = 0; tm < 4; tm++)
                LDSM4(ah[tm][0], ah[tm][1], ah[tm][2], ah[tm][3], st + rowOffA[tm] + chA);
            uint32_t chB = (uint32_t)(((kk * 2 + kHalfB) ^ l7) << 4);
            LDSM4(bh[0], bh[1], bh[2], bh[3], st + 16384 + rowOffB[0] + chB);
            LDSM4(bh[4], bh[5], bh[6], bh[7], st + 16384 + rowOffB[1] + chB);
            #pragma unroll
            for (int tm = 0; tm < 4; tm++)
                #pragma unroll
                for (int tn = 0; tn < 4; tn++)
                    MMA_F16(acc[tm][tn], ah[tm][0], ah[tm][1], ah[tm][2], ah[tm][3],
                            bh[2 * tn], bh[2 * tn + 1]);
        }
    }

    int g2 = lane >> 2, q2 = (lane & 3) * 2;
    size_t Nt = (size_t)gridDim.x * 128;
    #pragma unroll
    for (int tm = 0; tm < 4; tm++) {
        #pragma unroll
        for (int tn = 0; tn < 4; tn++) {
            int mg = m0 + wm * 64 + tm * 16 + g2;
            int cg = n0 + wn * 32 + tn * 8 + q2;
            size_t o0 = (size_t)mg * Nt + cg;
            size_t o1 = o0 + 8 * Nt;
            float* a = acc[tm][tn];
            float2 c0 = *(const float2*)(C + o0);
            float2 c1 = *(const float2*)(C + o1);
            c0.x += a[0]; c0.y += a[1];
            c1.x += a[2]; c1.y += a[3];
            *(float2*)(C + o0) = c0;
            *(float2*)(C + o1) = c1;
        }
    }
}

// ---------------------------------------------------------------------------
extern "C" void kernel_launch(void* const* d_in, const int* in_sizes, int n_in,
                              void* d_out, int out_size)
{
    const float* x        = (const float*)d_in[0];
    const float* router_w = (const float*)d_in[1];
    const float* w1       = (const float*)d_in[2];
    const float* w2       = (const float*)d_in[3];
    const float* w3       = (const float*)d_in[4];
    const float* lora_A   = (const float*)d_in[5];
    const float* lora_B   = (const float*)d_in[6];
    float* out = (float*)d_out;

    static bool init_done = false;
    static float *cc;
    static __half *xh, *b1, *b3, *b2, *a2;
    if (!init_done) {
        cudaGetSymbolAddress((void**)&cc, g_c);
        cudaGetSymbolAddress((void**)&xh, g_xh);
        cudaGetSymbolAddress((void**)&b1, g_b1);
        cudaGetSymbolAddress((void**)&b3, g_b3);
        cudaGetSymbolAddress((void**)&b2, g_b2);
        cudaGetSymbolAddress((void**)&a2, g_a2);
        cudaFuncSetAttribute(gemm_gateup_kernel,
                             cudaFuncAttributeMaxDynamicSharedMemorySize, FUSED_SMEM);
        cudaFuncSetAttribute(gemm_down_kernel,
                             cudaFuncAttributeMaxDynamicSharedMemorySize, GEMM_SMEM);
        init_done = true;
    }

    float* logits_out = nullptr;
    if ((size_t)out_size >= (size_t)NTOK * HDIM + (size_t)NTOK * NEXP)
        logits_out = out + (size_t)NTOK * HDIM;

    // merged prep: 3 weight transposes + router/LoRA/x-convert, one launch
    prep_kernel<<<TR_BLOCKS + NTOK, 256>>>(
        x, router_w, lora_A, logits_out, w1, w3, w2, b1, b3, b2);

    // LoRA GEMM initializes out (beta=0)
    sgemm128_kernel<<<dim3(HDIM / 128, NTOK / 128), 256>>>(cc, lora_B, out, NTOK, HDIM, NEXP * NR);

    // Fused gate+up: a2 = fp16(silu(x@w1) * (x@w3)), 128x64 tiles
    gemm_gateup_kernel<<<dim3(FDIM / 64, NTOK / 128), 256, FUSED_SMEM>>>(
        xh, b1, b3, a2, HDIM);

    // Down-proj: out += a2 @ w2 (128x128 tiles)
    gemm_down_kernel<<<dim3(HDIM / 128, NTOK / 128), 256, GEMM_SMEM>>>(
        a2, b2, out, FDIM);
}

// round 13
// speedup vs baseline: 1.0007x; 1.0007x over previous
#include <cuda_runtime.h>
#include <cuda_fp16.h>
#include <cstdint>
#include <math.h>

#define NTOK 4096
#define HDIM 4096
#define FDIM 14336
#define NEXP 8
#define NR   8
#define LSCALE 2.0f

#define TR_BLOCKS (3 * 28672)

// ---------------------------------------------------------------------------
// Scratch (__device__ globals; allocation-free rule)
// ---------------------------------------------------------------------------
__device__ __half g_xh[(size_t)NTOK * HDIM];   // x as fp16 [N,H]
__device__ __half g_b1[(size_t)FDIM * HDIM];   // w1^T [F,H] fp16
__device__ __half g_b3[(size_t)FDIM * HDIM];   // w3^T [F,H] fp16
__device__ __half g_b2[(size_t)HDIM * FDIM];   // w2^T [H,F] fp16
__device__ __half g_a2[(size_t)NTOK * FDIM];   // silu(gate)*up fp16 [N,F]
__device__ float  g_c[NTOK * NEXP * NR];       // LoRA coefficients

// ---------------------------------------------------------------------------
// Asm helpers (sm_80-level features; legal on plain sm_103 target)
// ---------------------------------------------------------------------------
__device__ __forceinline__ uint32_t smem_u32(const void* p) {
    uint32_t a;
    asm("{ .reg .u64 t; cvta.to.shared.u64 t, %1; cvt.u32.u64 %0, t; }" : "=r"(a) : "l"(p));
    return a;
}

#define CP16(dst, src) \
    asm volatile("cp.async.cg.shared.global [%0], [%1], 16;" :: "r"(dst), "l"(src))
#define CP_COMMIT() asm volatile("cp.async.commit_group;" ::: "memory")
#define CP_WAIT1()  asm volatile("cp.async.wait_group 1;" ::: "memory")

#define LDSM4(r0, r1, r2, r3, a) \
    asm volatile("ldmatrix.sync.aligned.m8n8.x4.shared.b16 {%0,%1,%2,%3}, [%4];" \
        : "=r"(r0), "=r"(r1), "=r"(r2), "=r"(r3) : "r"(a))

#define MMA_F16(c, a0, a1, a2, a3, b0, b1) \
    asm volatile("mma.sync.aligned.m16n8k16.row.col.f32.f16.f16.f32 " \
        "{%0,%1,%2,%3}, {%4,%5,%6,%7}, {%8,%9}, {%0,%1,%2,%3};" \
        : "+f"((c)[0]), "+f"((c)[1]), "+f"((c)[2]), "+f"((c)[3]) \
        : "r"(a0), "r"(a1), "r"(a2), "r"(a3), "r"(b0), "r"(b1))

// ---------------------------------------------------------------------------
// MERGED prep kernel: 1D grid.
//   bid < TR_BLOCKS  : weight transpose (w1 / w3 / w2 by range)
//   else             : router + LoRA coeffs + x fp16 conversion (token = bid-TR_BLOCKS)
// Shared memory is a union: transpose needs 8.5KB, router needs 24.6KB.
// ---------------------------------------------------------------------------
#define PREP_SMEM_BYTES ((HDIM + 8 * 32 * NR + 16) * 4)   // 24640 B

__global__ void __launch_bounds__(256) prep_kernel(
    const float* __restrict__ x, const float* __restrict__ router_w,
    const float* __restrict__ lora_A, float* __restrict__ logits_out,
    const float* __restrict__ w1, const float* __restrict__ w3,
    const float* __restrict__ w2,
    __half* __restrict__ b1, __half* __restrict__ b3, __half* __restrict__ b2)
{
    __shared__ __align__(16) char smraw[PREP_SMEM_BYTES];
    int bid = blockIdx.x;
    int tid = threadIdx.x;

    if (bid < TR_BLOCKS) {
        // ---------------- transpose path ----------------
        float (*t)[33] = reinterpret_cast<float(*)[33]>(smraw);
        int which = bid / 28672;
        int b     = bid % 28672;
        const float* W;
        __half* out;
        int K, N, nBlk;
        if (which == 0)      { W = w1; out = b1; K = HDIM; N = FDIM; nBlk = FDIM / 32; }
        else if (which == 1) { W = w3; out = b3; K = HDIM; N = FDIM; nBlk = FDIM / 32; }
        else                 { W = w2; out = b2; K = FDIM; N = HDIM; nBlk = HDIM / 32; }

        int n0 = (b % nBlk) * 32;
        int k0 = (b / nBlk) * 64;
        int tx = tid & 31, ty = tid >> 5;   // 32 x 8
        #pragma unroll
        for (int j = 0; j < 8; j++)
            t[ty + 8 * j][tx] = W[(size_t)(k0 + ty + 8 * j) * N + n0 + tx];
        __syncthreads();
        #pragma unroll
        for (int j = 0; j < 4; j++) {
            int n = ty + 8 * j;
            __half2 h = __floats2half2_rn(t[2 * tx][n], t[2 * tx + 1][n]);
            *(__half2*)(out + (size_t)(n0 + n) * K + k0 + 2 * tx) = h;
        }
        return;
    }

    // ---------------- router path (256 threads) ----------------
    int n = bid - TR_BLOCKS;
    float* xs = (float*)smraw;                                   // HDIM floats
    float (*red)[32][NR] = (float(*)[32][NR])(smraw + HDIM * 4); // 8 warps
    float* logits = (float*)(smraw + HDIM * 4 + 8 * 32 * NR * 4);
    int*   sel    = (int*)(logits + NEXP);
    float* rws    = (float*)(sel + 2);

    const float* xr = x + (size_t)n * HDIM;
    for (int i = tid; i < HDIM / 4; i += 256)
        ((float4*)xs)[i] = ((const float4*)xr)[i];
    __syncthreads();

    // fp16 conversion of x
    {
        __half* xo = g_xh + (size_t)n * HDIM;
        for (int i = tid; i < HDIM / 2; i += 256)
            *(__half2*)(xo + 2 * i) = __floats2half2_rn(xs[2 * i], xs[2 * i + 1]);
    }

    int wid = tid >> 5, lane = tid & 31;
    // logits: one expert per warp
    {
        int e = wid;
        const float* wr = router_w + (size_t)e * HDIM;
        float s = 0.f;
        for (int h = lane; h < HDIM; h += 32) s += xs[h] * wr[h];
        #pragma unroll
        for (int o = 16; o; o >>= 1) s += __shfl_down_sync(0xffffffffu, s, o);
        if (lane == 0) {
            logits[e] = s;
            if (logits_out) logits_out[(size_t)n * NEXP + e] = s;
        }
    }
    __syncthreads();

    if (tid == 0) {
        float m = -1e30f;
        for (int e = 0; e < NEXP; e++) m = fmaxf(m, logits[e]);
        float p[NEXP];
        for (int e = 0; e < NEXP; e++) p[e] = expf(logits[e] - m);
        int i0 = 0;
        for (int e = 1; e < NEXP; e++) if (p[e] > p[i0]) i0 = e;
        int i1 = -1;
        for (int e = 0; e < NEXP; e++) {
            if (e == i0) continue;
            if (i1 < 0 || p[e] > p[i1]) i1 = e;
        }
        float s2 = p[i0] + p[i1];
        sel[0] = i0; sel[1] = i1;
        rws[0] = p[i0] / s2; rws[1] = p[i1] / s2;
    }
    if (tid < NEXP * NR) g_c[n * NEXP * NR + tid] = 0.f;
    __syncthreads();

    // coalesced LoRA-A projection: warp -> (expert slot k = wid>>2, h-quarter)
    {
        int k = wid >> 2;                       // 0..1
        int q = wid & 3;                        // 0..3
        int e = sel[k];
        const float* A = lora_A + (size_t)e * HDIM * NR;
        float acc[NR];
        #pragma unroll
        for (int r = 0; r < NR; r++) acc[r] = 0.f;
        int h0 = q * (HDIM / 4);
        for (int it = 0; it < (HDIM / 4) / 32; it++) {
            int h = h0 + it * 32 + lane;
            const float4* ap = (const float4*)(A + (size_t)h * NR);
            float4 a0 = ap[0];
            float4 a1 = ap[1];
            float xv = xs[h];
            acc[0] += xv * a0.x; acc[1] += xv * a0.y;
            acc[2] += xv * a0.z; acc[3] += xv * a0.w;
            acc[4] += xv * a1.x; acc[5] += xv * a1.y;
            acc[6] += xv * a1.z; acc[7] += xv * a1.w;
        }
        #pragma unroll
        for (int r = 0; r < NR; r++) red[wid][lane][r] = acc[r];
    }
    __syncthreads();

    if (tid < 2 * NR) {
        int k = tid >> 3;
        int r = tid & 7;
        float s = 0.f;
        #pragma unroll
        for (int w = 0; w < 4; w++)
            for (int l = 0; l < 32; l++)
                s += red[4 * k + w][l][r];
        g_c[n * NEXP * NR + sel[k] * NR + r] = rws[k] * LSCALE * s;
    }
}

// ---------------------------------------------------------------------------
// Small fp32 SGEMM for LoRA (K=64), writes out with beta=0
// ---------------------------------------------------------------------------
__global__ void __launch_bounds__(256) sgemm128_kernel(
    const float* __restrict__ A, const float* __restrict__ B,
    float* __restrict__ C, int M, int N, int K)
{
    __shared__ float As[8][128];
    __shared__ float Bs[8][128];
    int tid = threadIdx.x;
    int m0 = blockIdx.y * 128, n0 = blockIdx.x * 128;
    int aRow = tid >> 1, aCol = (tid & 1) * 4;
    int bRow = tid >> 5, bCol = (tid & 31) * 4;
    const float* Aptr = A + (size_t)(m0 + aRow) * K + aCol;
    const float* Bptr = B + (size_t)bRow * N + n0 + bCol;
    int ty = tid >> 4, tx = tid & 15;

    float acc[8][8];
    #pragma unroll
    for (int i = 0; i < 8; i++)
        #pragma unroll
        for (int j = 0; j < 8; j++) acc[i][j] = 0.f;

    for (int k0 = 0; k0 < K; k0 += 8) {
        float4 av = *(const float4*)Aptr; Aptr += 8;
        float4 bv = *(const float4*)Bptr; Bptr += (size_t)8 * N;
        As[aCol + 0][aRow] = av.x; As[aCol + 1][aRow] = av.y;
        As[aCol + 2][aRow] = av.z; As[aCol + 3][aRow] = av.w;
        *(float4*)&Bs[bRow][bCol] = bv;
        __syncthreads();
        #pragma unroll
        for (int kk = 0; kk < 8; kk++) {
            float a[8], b[8];
            *(float4*)(a)     = *(const float4*)&As[kk][ty * 8];
            *(float4*)(a + 4) = *(const float4*)&As[kk][ty * 8 + 4];
            *(float4*)(b)     = *(const float4*)&Bs[kk][tx * 8];
            *(float4*)(b + 4) = *(const float4*)&Bs[kk][tx * 8 + 4];
            #pragma unroll
            for (int i = 0; i < 8; i++)
                #pragma unroll
                for (int j = 0; j < 8; j++)
                    acc[i][j] = fmaf(a[i], b[j], acc[i][j]);
        }
        __syncthreads();
    }
    #pragma unroll
    for (int i = 0; i < 8; i++) {
        float* Cr = C + (size_t)(m0 + ty * 8 + i) * N + n0 + tx * 8;
        *(float4*)Cr       = make_float4(acc[i][0], acc[i][1], acc[i][2], acc[i][3]);
        *(float4*)(Cr + 4) = make_float4(acc[i][4], acc[i][5], acc[i][6], acc[i][7]);
    }
}

// ---------------------------------------------------------------------------
// FUSED gate+up GEMM, 128m x 64n CTA tile (occ=2).
// ---------------------------------------------------------------------------
#define FSTG 32768
#define FUSED_SMEM (3 * FSTG)

__device__ __forceinline__ void issue_stage_gu(
    uint32_t st, const __half* A, const __half* B1, const __half* B3,
    int m0, int n0, int kpos, int K, int lr, int lkc)
{
    #pragma unroll
    for (int rr = 0; rr < 256; rr += 32) {
        int row = lr + rr;
        uint32_t so = row * 128 + ((lkc ^ (row & 7)) << 4);
        const __half* src;
        if (rr < 128)      src = A  + (size_t)(m0 + row) * K;
        else if (rr < 192) src = B1 + (size_t)(n0 + row - 128) * K;
        else               src = B3 + (size_t)(n0 + row - 192) * K;
        CP16(st + so, src + kpos + lkc * 8);
    }
    CP_COMMIT();
}

__global__ void __launch_bounds__(256, 2) gemm_gateup_kernel(
    const __half* __restrict__ A, const __half* __restrict__ B1,
    const __half* __restrict__ B3, __half* __restrict__ oA2, int K)
{
    extern __shared__ __align__(1024) char smem[];
    uint32_t sb = smem_u32(smem);
    int tid = threadIdx.x;
    int wid = tid >> 5, lane = tid & 31;
    int wm = wid >> 2, wn = wid & 3;

    int lin = blockIdx.y * gridDim.x + blockIdx.x;
    int gs  = 8 * gridDim.y;
    int g   = lin / gs, r = lin - g * gs;
    int m0  = (r >> 3) * 128;
    int n0  = (g * 8 + (r & 7)) * 64;

    int NT = K >> 6;
    int lr = tid >> 3, lkc = tid & 7;

    int laneM  = lane & 15;
    int kHalfA = lane >> 4;
    int aSw    = laneM & 7;
    uint32_t rowOffA[4];
    #pragma unroll
    for (int tm = 0; tm < 4; tm++)
        rowOffA[tm] = (uint32_t)(wm * 64 + tm * 16 + laneM) * 128;
    int l7     = lane & 7;
    int kHalfB = (lane >> 3) & 1;
    uint32_t rowB = (uint32_t)(wn * 16 + ((lane >> 4) & 1) * 8 + l7) * 128;

    float accG[4][2][4], accU[4][2][4];
    #pragma unroll
    for (int i = 0; i < 4; i++)
        #pragma unroll
        for (int j = 0; j < 2; j++)
            #pragma unroll
            for (int q = 0; q < 4; q++) { accG[i][j][q] = 0.f; accU[i][j][q] = 0.f; }

    issue_stage_gu(sb,        A, B1, B3, m0, n0, 0,  K, lr, lkc);
    issue_stage_gu(sb + FSTG, A, B1, B3, m0, n0, 64, K, lr, lkc);

    for (int kt = 0; kt < NT; kt++) {
        CP_WAIT1();
        __syncthreads();
        if (kt + 2 < NT)
            issue_stage_gu(sb + ((kt + 2) % 3) * FSTG, A, B1, B3,
                           m0, n0, (kt + 2) << 6, K, lr, lkc);
        else
            CP_COMMIT();

        uint32_t st = sb + (kt % 3) * FSTG;
        #pragma unroll
        for (int kk = 0; kk < 4; kk++) {
            uint32_t ah[4][4], b1f[4], b3f[4];
            uint32_t chA = (uint32_t)(((kk * 2 + kHalfA) ^ aSw) << 4);
            #pragma unroll
            for (int tm = 0; tm < 4; tm++)
                LDSM4(ah[tm][0], ah[tm][1], ah[tm][2], ah[tm][3], st + rowOffA[tm] + chA);
            uint32_t chB = (uint32_t)(((kk * 2 + kHalfB) ^ l7) << 4);
            LDSM4(b1f[0], b1f[1], b1f[2], b1f[3], st + 16384 + rowB + chB);
            LDSM4(b3f[0], b3f[1], b3f[2], b3f[3], st + 24576 + rowB + chB);
            #pragma unroll
            for (int tm = 0; tm < 4; tm++)
                #pragma unroll
                for (int tn = 0; tn < 2; tn++) {
                    MMA_F16(accG[tm][tn], ah[tm][0], ah[tm][1], ah[tm][2], ah[tm][3],
                            b1f[2 * tn], b1f[2 * tn + 1]);
                    MMA_F16(accU[tm][tn], ah[tm][0], ah[tm][1], ah[tm][2], ah[tm][3],
                            b3f[2 * tn], b3f[2 * tn + 1]);
                }
        }
    }

    int g2 = lane >> 2, q2 = (lane & 3) * 2;
    size_t Nt = (size_t)gridDim.x * 64;
    #pragma unroll
    for (int tm = 0; tm < 4; tm++) {
        #pragma unroll
        for (int tn = 0; tn < 2; tn++) {
            int mg = m0 + wm * 64 + tm * 16 + g2;
            int cg = n0 + wn * 16 + tn * 8 + q2;
            size_t o0 = (size_t)mg * Nt + cg;
            size_t o1 = o0 + 8 * Nt;
            float* gg = accG[tm][tn];
            float* uu = accU[tm][tn];
            float v0 = gg[0] / (1.f + __expf(-gg[0])) * uu[0];
            float v1 = gg[1] / (1.f + __expf(-gg[1])) * uu[1];
            float v2 = gg[2] / (1.f + __expf(-gg[2])) * uu[2];
            float v3 = gg[3] / (1.f + __expf(-gg[3])) * uu[3];
            *(__half2*)(oA2 + o0) = __floats2half2_rn(v0, v1);
            *(__half2*)(oA2 + o1) = __floats2half2_rn(v2, v3);
        }
    }
}

// ---------------------------------------------------------------------------
// Down-projection fp16 GEMM (accumulate onto out): C += A @ B^T
// 128x128 tile, occ=2, raster swizzle.
// ---------------------------------------------------------------------------
#define STAGE_BYTES 32768
#define GEMM_SMEM   (3 * STAGE_BYTES)

__device__ __forceinline__ void issue_stage_f16(
    uint32_t st, const __half* A, const __half* B,
    int m0, int n0, int kpos, int K, int lr, int lkc)
{
    #pragma unroll
    for (int rr = 0; rr < 128; rr += 32) {
        int row = lr + rr;
        uint32_t so = row * 128 + ((lkc ^ (row & 7)) << 4);
        size_t ga = (size_t)(m0 + row) * K + kpos + lkc * 8;
        size_t gb = (size_t)(n0 + row) * K + kpos + lkc * 8;
        CP16(st + so,         A + ga);
        CP16(st + 16384 + so, B + gb);
    }
    CP_COMMIT();
}

__global__ void __launch_bounds__(256, 2) gemm_down_kernel(
    const __half* __restrict__ A, const __half* __restrict__ B,
    float* __restrict__ C, int K)
{
    extern __shared__ __align__(1024) char smem[];
    uint32_t sb = smem_u32(smem);
    int tid = threadIdx.x;
    int wid = tid >> 5, lane = tid & 31;
    int wm = wid >> 2, wn = wid & 3;

    int lin = blockIdx.y * gridDim.x + blockIdx.x;
    int gs  = 8 * gridDim.y;
    int g   = lin / gs, r = lin - g * gs;
    int m0  = (r >> 3) * 128;
    int n0  = (g * 8 + (r & 7)) * 128;

    int NT = K >> 6;
    int lr = tid >> 3, lkc = tid & 7;

    int laneM  = lane & 15;
    int kHalfA = lane >> 4;
    int aSw    = laneM & 7;
    uint32_t rowOffA[4];
    #pragma unroll
    for (int tm = 0; tm < 4; tm++)
        rowOffA[tm] = (uint32_t)(wm * 64 + tm * 16 + laneM) * 128;
    int l7     = lane & 7;
    int kHalfB = (lane >> 3) & 1;
    uint32_t rowOffB[2];
    #pragma unroll
    for (int pr = 0; pr < 2; pr++)
        rowOffB[pr] = (uint32_t)(wn * 32 + pr * 16 + ((lane >> 4) & 1) * 8 + l7) * 128;

    float acc[4][4][4];
    #pragma unroll
    for (int i = 0; i < 4; i++)
        #pragma unroll
        for (int j = 0; j < 4; j++)
            #pragma unroll
            for (int q = 0; q < 4; q++) acc[i][j][q] = 0.f;

    issue_stage_f16(sb,               A, B, m0, n0, 0,  K, lr, lkc);
    issue_stage_f16(sb + STAGE_BYTES, A, B, m0, n0, 64, K, lr, lkc);

    for (int kt = 0; kt < NT; kt++) {
        CP_WAIT1();
        __syncthreads();
        if (kt + 2 < NT)
            issue_stage_f16(sb + ((kt + 2) % 3) * STAGE_BYTES, A, B,
                            m0, n0, (kt + 2) << 6, K, lr, lkc);
        else
            CP_COMMIT();

        uint32_t st = sb + (kt % 3) * STAGE_BYTES;
        #pragma unroll
        for (int kk = 0; kk < 4; kk++) {
            uint32_t ah[4][4], bh[8];
            uint32_t chA = (uint32_t)(((kk * 2 + kHalfA) ^ aSw) << 4);
            #pragma unroll
            for (int tm = 0; tm < 4; tm++)
                LDSM4(ah[tm][0], ah[tm][1], ah[tm][2], ah[tm][3], st + rowOffA[tm] + chA);
            uint32_t chB = (uint32_t)(((kk * 2 + kHalfB) ^ l7) << 4);
            LDSM4(bh[0], bh[1], bh[2], bh[3], st + 16384 + rowOffB[0] + chB);
            LDSM4(bh[4], bh[5], bh[6], bh[7], st + 16384 + rowOffB[1] + chB);
            #pragma unroll
            for (int tm = 0; tm < 4; tm++)
                #pragma unroll
                for (int tn = 0; tn < 4; tn++)
                    MMA_F16(acc[tm][tn], ah[tm][0], ah[tm][1], ah[tm][2], ah[tm][3],
                            bh[2 * tn], bh[2 * tn + 1]);
        }
    }

    int g2 = lane >> 2, q2 = (lane & 3) * 2;
    size_t Nt = (size_t)gridDim.x * 128;
    #pragma unroll
    for (int tm = 0; tm < 4; tm++) {
        #pragma unroll
        for (int tn = 0; tn < 4; tn++) {
            int mg = m0 + wm * 64 + tm * 16 + g2;
            int cg = n0 + wn * 32 + tn * 8 + q2;
            size_t o0 = (size_t)mg * Nt + cg;
            size_t o1 = o0 + 8 * Nt;
            float* a = acc[tm][tn];
            float2 c0 = *(const float2*)(C + o0);
            float2 c1 = *(const float2*)(C + o1);
            c0.x += a[0]; c0.y += a[1];
            c1.x += a[2]; c1.y += a[3];
            *(float2*)(C + o0) = c0;
            *(float2*)(C + o1) = c1;
        }
    }
}

// ---------------------------------------------------------------------------
extern "C" void kernel_launch(void* const* d_in, const int* in_sizes, int n_in,
                              void* d_out, int out_size)
{
    const float* x        = (const float*)d_in[0];
    const float* router_w = (const float*)d_in[1];
    const float* w1       = (const float*)d_in[2];
    const float* w2       = (const float*)d_in[3];
    const float* w3       = (const float*)d_in[4];
    const float* lora_A   = (const float*)d_in[5];
    const float* lora_B   = (const float*)d_in[6];
    float* out = (float*)d_out;

    static bool init_done = false;
    static float *cc;
    static __half *xh, *b1, *b3, *b2, *a2;
    if (!init_done) {
        cudaGetSymbolAddress((void**)&cc, g_c);
        cudaGetSymbolAddress((void**)&xh, g_xh);
        cudaGetSymbolAddress((void**)&b1, g_b1);
        cudaGetSymbolAddress((void**)&b3, g_b3);
        cudaGetSymbolAddress((void**)&b2, g_b2);
        cudaGetSymbolAddress((void**)&a2, g_a2);
        cudaFuncSetAttribute(gemm_gateup_kernel,
                             cudaFuncAttributeMaxDynamicSharedMemorySize, FUSED_SMEM);
        cudaFuncSetAttribute(gemm_down_kernel,
                             cudaFuncAttributeMaxDynamicSharedMemorySize, GEMM_SMEM);
        init_done = true;
    }

    float* logits_out = nullptr;
    if ((size_t)out_size >= (size_t)NTOK * HDIM + (size_t)NTOK * NEXP)
        logits_out = out + (size_t)NTOK * HDIM;

    // merged prep: 3 weight transposes + router/LoRA/x-convert, one launch
    prep_kernel<<<TR_BLOCKS + NTOK, 256>>>(
        x, router_w, lora_A, logits_out, w1, w3, w2, b1, b3, b2);

    // LoRA GEMM initializes out (beta=0)
    sgemm128_kernel<<<dim3(HDIM / 128, NTOK / 128), 256>>>(cc, lora_B, out, NTOK, HDIM, NEXP * NR);

    // Fused gate+up: a2 = fp16(silu(x@w1) * (x@w3)), 128x64 tiles
    gemm_gateup_kernel<<<dim3(FDIM / 64, NTOK / 128), 256, FUSED_SMEM>>>(
        xh, b1, b3, a2, HDIM);

    // Down-proj: out += a2 @ w2 (128x128 tiles)
    gemm_down_kernel<<<dim3(HDIM / 128, NTOK / 128), 256, GEMM_SMEM>>>(
        a2, b2, out, FDIM);
}

// round 14
// speedup vs baseline: 1.0253x; 1.0245x over previous
#include <cuda_runtime.h>
#include <cuda_fp16.h>
#include <cstdint>
#include <math.h>

#define NTOK 4096
#define HDIM 4096
#define FDIM 14336
#define NEXP 8
#define NR   8
#define LSCALE 2.0f

#define TR_BLOCKS  (3 * 28672)
#define TRL_BLOCKS (TR_BLOCKS + 128)   // + lora_B transpose

// ---------------------------------------------------------------------------
// Scratch (__device__ globals; allocation-free rule)
// ---------------------------------------------------------------------------
__device__ __half g_xh[(size_t)NTOK * HDIM];    // x as fp16 [N,H]
__device__ __half g_b1[(size_t)FDIM * HDIM];    // w1^T [F,H] fp16
__device__ __half g_b3[(size_t)FDIM * HDIM];    // w3^T [F,H] fp16
__device__ __half g_b2[(size_t)HDIM * FDIM];    // w2^T [H,F] fp16
__device__ __half g_a2[(size_t)NTOK * FDIM];    // silu(gate)*up fp16 [N,F]
__device__ __half g_c16[(size_t)NTOK * 64];     // LoRA coeffs fp16 [N,64]
__device__ __half g_lbT[(size_t)HDIM * 64];     // lora_B^T [H,64] fp16

// ---------------------------------------------------------------------------
// Asm helpers (sm_80-level features; legal on plain sm_103 target)
// ---------------------------------------------------------------------------
__device__ __forceinline__ uint32_t smem_u32(const void* p) {
    uint32_t a;
    asm("{ .reg .u64 t; cvta.to.shared.u64 t, %1; cvt.u32.u64 %0, t; }" : "=r"(a) : "l"(p));
    return a;
}

#define CP16(dst, src) \
    asm volatile("cp.async.cg.shared.global [%0], [%1], 16;" :: "r"(dst), "l"(src))
#define CP_COMMIT() asm volatile("cp.async.commit_group;" ::: "memory")
#define CP_WAIT1()  asm volatile("cp.async.wait_group 1;" ::: "memory")

#define LDSM4(r0, r1, r2, r3, a) \
    asm volatile("ldmatrix.sync.aligned.m8n8.x4.shared.b16 {%0,%1,%2,%3}, [%4];" \
        : "=r"(r0), "=r"(r1), "=r"(r2), "=r"(r3) : "r"(a))

#define MMA_F16(c, a0, a1, a2, a3, b0, b1) \
    asm volatile("mma.sync.aligned.m16n8k16.row.col.f32.f16.f16.f32 " \
        "{%0,%1,%2,%3}, {%4,%5,%6,%7}, {%8,%9}, {%0,%1,%2,%3};" \
        : "+f"((c)[0]), "+f"((c)[1]), "+f"((c)[2]), "+f"((c)[3]) \
        : "r"(a0), "r"(a1), "r"(a2), "r"(a3), "r"(b0), "r"(b1))

// ---------------------------------------------------------------------------
// MERGED prep kernel (1D grid):
//   bid < TR_BLOCKS      : w1/w3/w2 transpose+convert
//   bid < TRL_BLOCKS     : lora_B [64,4096] -> [4096,64] fp16
//   else                 : router + LoRA coeffs (fp16) + x fp16 conversion
// ---------------------------------------------------------------------------
#define PREP_SMEM_BYTES ((HDIM + 8 * 32 * NR + 16) * 4)   // 24640 B

__global__ void __launch_bounds__(256) prep_kernel(
    const float* __restrict__ x, const float* __restrict__ router_w,
    const float* __restrict__ lora_A, const float* __restrict__ lora_B,
    float* __restrict__ logits_out,
    const float* __restrict__ w1, const float* __restrict__ w3,
    const float* __restrict__ w2,
    __half* __restrict__ b1, __half* __restrict__ b3, __half* __restrict__ b2)
{
    __shared__ __align__(16) char smraw[PREP_SMEM_BYTES];
    int bid = blockIdx.x;
    int tid = threadIdx.x;

    if (bid < TRL_BLOCKS) {
        // ---------------- transpose path ----------------
        float (*t)[33] = reinterpret_cast<float(*)[33]>(smraw);
        int which = bid / 28672;        // 0,1,2 big weights; 3 = lora_B (128 blocks)
        int b     = bid % 28672;
        const float* W;
        __half* out;
        int K, N, nBlk;
        if (which == 0)      { W = w1;     out = b1;    K = HDIM; N = FDIM; nBlk = FDIM / 32; }
        else if (which == 1) { W = w3;     out = b3;    K = HDIM; N = FDIM; nBlk = FDIM / 32; }
        else if (which == 2) { W = w2;     out = b2;    K = FDIM; N = HDIM; nBlk = HDIM / 32; }
        else                 { W = lora_B; out = g_lbT; K = 64;   N = HDIM; nBlk = HDIM / 32; }

        int n0 = (b % nBlk) * 32;
        int k0 = (b / nBlk) * 64;
        int tx = tid & 31, ty = tid >> 5;   // 32 x 8
        #pragma unroll
        for (int j = 0; j < 8; j++)
            t[ty + 8 * j][tx] = W[(size_t)(k0 + ty + 8 * j) * N + n0 + tx];
        __syncthreads();
        #pragma unroll
        for (int j = 0; j < 4; j++) {
            int n = ty + 8 * j;
            __half2 h = __floats2half2_rn(t[2 * tx][n], t[2 * tx + 1][n]);
            *(__half2*)(out + (size_t)(n0 + n) * K + k0 + 2 * tx) = h;
        }
        return;
    }

    // ---------------- router path (256 threads) ----------------
    int n = bid - TRL_BLOCKS;
    float* xs = (float*)smraw;                                   // HDIM floats
    float (*red)[32][NR] = (float(*)[32][NR])(smraw + HDIM * 4); // 8 warps
    float* logits = (float*)(smraw + HDIM * 4 + 8 * 32 * NR * 4);
    int*   sel    = (int*)(logits + NEXP);
    float* rws    = (float*)(sel + 2);

    const float* xr = x + (size_t)n * HDIM;
    for (int i = tid; i < HDIM / 4; i += 256)
        ((float4*)xs)[i] = ((const float4*)xr)[i];
    __syncthreads();

    // fp16 conversion of x
    {
        __half* xo = g_xh + (size_t)n * HDIM;
        for (int i = tid; i < HDIM / 2; i += 256)
            *(__half2*)(xo + 2 * i) = __floats2half2_rn(xs[2 * i], xs[2 * i + 1]);
    }

    int wid = tid >> 5, lane = tid & 31;
    // logits: one expert per warp
    {
        int e = wid;
        const float* wr = router_w + (size_t)e * HDIM;
        float s = 0.f;
        for (int h = lane; h < HDIM; h += 32) s += xs[h] * wr[h];
        #pragma unroll
        for (int o = 16; o; o >>= 1) s += __shfl_down_sync(0xffffffffu, s, o);
        if (lane == 0) {
            logits[e] = s;
            if (logits_out) logits_out[(size_t)n * NEXP + e] = s;
        }
    }
    __syncthreads();

    if (tid == 0) {
        float m = -1e30f;
        for (int e = 0; e < NEXP; e++) m = fmaxf(m, logits[e]);
        float p[NEXP];
        for (int e = 0; e < NEXP; e++) p[e] = expf(logits[e] - m);
        int i0 = 0;
        for (int e = 1; e < NEXP; e++) if (p[e] > p[i0]) i0 = e;
        int i1 = -1;
        for (int e = 0; e < NEXP; e++) {
            if (e == i0) continue;
            if (i1 < 0 || p[e] > p[i1]) i1 = e;
        }
        float s2 = p[i0] + p[i1];
        sel[0] = i0; sel[1] = i1;
        rws[0] = p[i0] / s2; rws[1] = p[i1] / s2;
    }
    // zero fp16 coefficient row (64 halves = 32 half2)
    if (tid < 32) {
        __half2 z; z.x = __float2half(0.f); z.y = __float2half(0.f);
        ((__half2*)(g_c16 + (size_t)n * 64))[tid] = z;
    }
    __syncthreads();

    // coalesced LoRA-A projection: warp -> (expert slot k = wid>>2, h-quarter)
    {
        int k = wid >> 2;                       // 0..1
        int q = wid & 3;                        // 0..3
        int e = sel[k];
        const float* A = lora_A + (size_t)e * HDIM * NR;
        float acc[NR];
        #pragma unroll
        for (int r = 0; r < NR; r++) acc[r] = 0.f;
        int h0 = q * (HDIM / 4);
        for (int it = 0; it < (HDIM / 4) / 32; it++) {
            int h = h0 + it * 32 + lane;
            const float4* ap = (const float4*)(A + (size_t)h * NR);
            float4 a0 = ap[0];
            float4 a1 = ap[1];
            float xv = xs[h];
            acc[0] += xv * a0.x; acc[1] += xv * a0.y;
            acc[2] += xv * a0.z; acc[3] += xv * a0.w;
            acc[4] += xv * a1.x; acc[5] += xv * a1.y;
            acc[6] += xv * a1.z; acc[7] += xv * a1.w;
        }
        #pragma unroll
        for (int r = 0; r < NR; r++) red[wid][lane][r] = acc[r];
    }
    __syncthreads();

    if (tid < 2 * NR) {
        int k = tid >> 3;
        int r = tid & 7;
        float s = 0.f;
        #pragma unroll
        for (int w = 0; w < 4; w++)
            for (int l = 0; l < 32; l++)
                s += red[4 * k + w][l][r];
        g_c16[(size_t)n * 64 + sel[k] * NR + r] = __float2half(rws[k] * LSCALE * s);
    }
}

// ---------------------------------------------------------------------------
// FUSED gate+up GEMM, 128m x 64n CTA tile (occ=2). (unchanged from round 10)
// ---------------------------------------------------------------------------
#define FSTG 32768
#define FUSED_SMEM (3 * FSTG)

__device__ __forceinline__ void issue_stage_gu(
    uint32_t st, const __half* A, const __half* B1, const __half* B3,
    int m0, int n0, int kpos, int K, int lr, int lkc)
{
    #pragma unroll
    for (int rr = 0; rr < 256; rr += 32) {
        int row = lr + rr;
        uint32_t so = row * 128 + ((lkc ^ (row & 7)) << 4);
        const __half* src;
        if (rr < 128)      src = A  + (size_t)(m0 + row) * K;
        else if (rr < 192) src = B1 + (size_t)(n0 + row - 128) * K;
        else               src = B3 + (size_t)(n0 + row - 192) * K;
        CP16(st + so, src + kpos + lkc * 8);
    }
    CP_COMMIT();
}

__global__ void __launch_bounds__(256, 2) gemm_gateup_kernel(
    const __half* __restrict__ A, const __half* __restrict__ B1,
    const __half* __restrict__ B3, __half* __restrict__ oA2, int K)
{
    extern __shared__ __align__(1024) char smem[];
    uint32_t sb = smem_u32(smem);
    int tid = threadIdx.x;
    int wid = tid >> 5, lane = tid & 31;
    int wm = wid >> 2, wn = wid & 3;

    int lin = blockIdx.y * gridDim.x + blockIdx.x;
    int gs  = 8 * gridDim.y;
    int g   = lin / gs, r = lin - g * gs;
    int m0  = (r >> 3) * 128;
    int n0  = (g * 8 + (r & 7)) * 64;

    int NT = K >> 6;
    int lr = tid >> 3, lkc = tid & 7;

    int laneM  = lane & 15;
    int kHalfA = lane >> 4;
    int aSw    = laneM & 7;
    uint32_t rowOffA[4];
    #pragma unroll
    for (int tm = 0; tm < 4; tm++)
        rowOffA[tm] = (uint32_t)(wm * 64 + tm * 16 + laneM) * 128;
    int l7     = lane & 7;
    int kHalfB = (lane >> 3) & 1;
    uint32_t rowB = (uint32_t)(wn * 16 + ((lane >> 4) & 1) * 8 + l7) * 128;

    float accG[4][2][4], accU[4][2][4];
    #pragma unroll
    for (int i = 0; i < 4; i++)
        #pragma unroll
        for (int j = 0; j < 2; j++)
            #pragma unroll
            for (int q = 0; q < 4; q++) { accG[i][j][q] = 0.f; accU[i][j][q] = 0.f; }

    issue_stage_gu(sb,        A, B1, B3, m0, n0, 0,  K, lr, lkc);
    issue_stage_gu(sb + FSTG, A, B1, B3, m0, n0, 64, K, lr, lkc);

    for (int kt = 0; kt < NT; kt++) {
        CP_WAIT1();
        __syncthreads();
        if (kt + 2 < NT)
            issue_stage_gu(sb + ((kt + 2) % 3) * FSTG, A, B1, B3,
                           m0, n0, (kt + 2) << 6, K, lr, lkc);
        else
            CP_COMMIT();

        uint32_t st = sb + (kt % 3) * FSTG;
        #pragma unroll
        for (int kk = 0; kk < 4; kk++) {
            uint32_t ah[4][4], b1f[4], b3f[4];
            uint32_t chA = (uint32_t)(((kk * 2 + kHalfA) ^ aSw) << 4);
            #pragma unroll
            for (int tm = 0; tm < 4; tm++)
                LDSM4(ah[tm][0], ah[tm][1], ah[tm][2], ah[tm][3], st + rowOffA[tm] + chA);
            uint32_t chB = (uint32_t)(((kk * 2 + kHalfB) ^ l7) << 4);
            LDSM4(b1f[0], b1f[1], b1f[2], b1f[3], st + 16384 + rowB + chB);
            LDSM4(b3f[0], b3f[1], b3f[2], b3f[3], st + 24576 + rowB + chB);
            #pragma unroll
            for (int tm = 0; tm < 4; tm++)
                #pragma unroll
                for (int tn = 0; tn < 2; tn++) {
                    MMA_F16(accG[tm][tn], ah[tm][0], ah[tm][1], ah[tm][2], ah[tm][3],
                            b1f[2 * tn], b1f[2 * tn + 1]);
                    MMA_F16(accU[tm][tn], ah[tm][0], ah[tm][1], ah[tm][2], ah[tm][3],
                            b3f[2 * tn], b3f[2 * tn + 1]);
                }
        }
    }

    int g2 = lane >> 2, q2 = (lane & 3) * 2;
    size_t Nt = (size_t)gridDim.x * 64;
    #pragma unroll
    for (int tm = 0; tm < 4; tm++) {
        #pragma unroll
        for (int tn = 0; tn < 2; tn++) {
            int mg = m0 + wm * 64 + tm * 16 + g2;
            int cg = n0 + wn * 16 + tn * 8 + q2;
            size_t o0 = (size_t)mg * Nt + cg;
            size_t o1 = o0 + 8 * Nt;
            float* gg = accG[tm][tn];
            float* uu = accU[tm][tn];
            float v0 = gg[0] / (1.f + __expf(-gg[0])) * uu[0];
            float v1 = gg[1] / (1.f + __expf(-gg[1])) * uu[1];
            float v2 = gg[2] / (1.f + __expf(-gg[2])) * uu[2];
            float v3 = gg[3] / (1.f + __expf(-gg[3])) * uu[3];
            *(__half2*)(oA2 + o0) = __floats2half2_rn(v0, v1);
            *(__half2*)(oA2 + o1) = __floats2half2_rn(v2, v3);
        }
    }
}

// ---------------------------------------------------------------------------
// Down-projection + LoRA fp16 GEMM (writes out, beta=0):
//   out = c16 @ lbT^T  +  a2 @ b2^T
// Chunk 0 streams c16/lbT (row stride 64), chunks 1..K/64 stream a2/b2.
// 128x128 tile, occ=2, raster swizzle.
// ---------------------------------------------------------------------------
#define STAGE_BYTES 32768
#define GEMM_SMEM   (3 * STAGE_BYTES)

__device__ __forceinline__ void issue_stage_dn(
    uint32_t st, const __half* A, const __half* B,
    const __half* cA, const __half* cB,
    int m0, int n0, int ci, int K, int lr, int lkc)
{
    #pragma unroll
    for (int rr = 0; rr < 128; rr += 32) {
        int row = lr + rr;
        uint32_t so = row * 128 + ((lkc ^ (row & 7)) << 4);
        const __half* sA;
        const __half* sB;
        if (ci == 0) {
            sA = cA + (size_t)(m0 + row) * 64 + lkc * 8;
            sB = cB + (size_t)(n0 + row) * 64 + lkc * 8;
        } else {
            int kpos = (ci - 1) << 6;
            sA = A + (size_t)(m0 + row) * K + kpos + lkc * 8;
            sB = B + (size_t)(n0 + row) * K + kpos + lkc * 8;
        }
        CP16(st + so,         sA);
        CP16(st + 16384 + so, sB);
    }
    CP_COMMIT();
}

__global__ void __launch_bounds__(256, 2) gemm_down_kernel(
    const __half* __restrict__ A, const __half* __restrict__ B,
    const __half* __restrict__ cA, const __half* __restrict__ cB,
    float* __restrict__ C, int K)
{
    extern __shared__ __align__(1024) char smem[];
    uint32_t sb = smem_u32(smem);
    int tid = threadIdx.x;
    int wid = tid >> 5, lane = tid & 31;
    int wm = wid >> 2, wn = wid & 3;

    int lin = blockIdx.y * gridDim.x + blockIdx.x;
    int gs  = 8 * gridDim.y;
    int g   = lin / gs, r = lin - g * gs;
    int m0  = (r >> 3) * 128;
    int n0  = (g * 8 + (r & 7)) * 128;

    int NCH = (K >> 6) + 1;   // 1 LoRA chunk + K/64 main chunks
    int lr = tid >> 3, lkc = tid & 7;

    int laneM  = lane & 15;
    int kHalfA = lane >> 4;
    int aSw    = laneM & 7;
    uint32_t rowOffA[4];
    #pragma unroll
    for (int tm = 0; tm < 4; tm++)
        rowOffA[tm] = (uint32_t)(wm * 64 + tm * 16 + laneM) * 128;
    int l7     = lane & 7;
    int kHalfB = (lane >> 3) & 1;
    uint32_t rowOffB[2];
    #pragma unroll
    for (int pr = 0; pr < 2; pr++)
        rowOffB[pr] = (uint32_t)(wn * 32 + pr * 16 + ((lane >> 4) & 1) * 8 + l7) * 128;

    float acc[4][4][4];
    #pragma unroll
    for (int i = 0; i < 4; i++)
        #pragma unroll
        for (int j = 0; j < 4; j++)
            #pragma unroll
            for (int q = 0; q < 4; q++) acc[i][j][q] = 0.f;

    issue_stage_dn(sb,               A, B, cA, cB, m0, n0, 0, K, lr, lkc);
    issue_stage_dn(sb + STAGE_BYTES, A, B, cA, cB, m0, n0, 1, K, lr, lkc);

    for (int ci = 0; ci < NCH; ci++) {
        CP_WAIT1();
        __syncthreads();
        if (ci + 2 < NCH)
            issue_stage_dn(sb + ((ci + 2) % 3) * STAGE_BYTES, A, B, cA, cB,
                           m0, n0, ci + 2, K, lr, lkc);
        else
            CP_COMMIT();

        uint32_t st = sb + (ci % 3) * STAGE_BYTES;
        #pragma unroll
        for (int kk = 0; kk < 4; kk++) {
            uint32_t ah[4][4], bh[8];
            uint32_t chA = (uint32_t)(((kk * 2 + kHalfA) ^ aSw) << 4);
            #pragma unroll
            for (int tm = 0; tm < 4; tm++)
                LDSM4(ah[tm][0], ah[tm][1], ah[tm][2], ah[tm][3], st + rowOffA[tm] + chA);
            uint32_t chB = (uint32_t)(((kk * 2 + kHalfB) ^ l7) << 4);
            LDSM4(bh[0], bh[1], bh[2], bh[3], st + 16384 + rowOffB[0] + chB);
            LDSM4(bh[4], bh[5], bh[6], bh[7], st + 16384 + rowOffB[1] + chB);
            #pragma unroll
            for (int tm = 0; tm < 4; tm++)
                #pragma unroll
                for (int tn = 0; tn < 4; tn++)
                    MMA_F16(acc[tm][tn], ah[tm][0], ah[tm][1], ah[tm][2], ah[tm][3],
                            bh[2 * tn], bh[2 * tn + 1]);
        }
    }

    int g2 = lane >> 2, q2 = (lane & 3) * 2;
    size_t Nt = (size_t)gridDim.x * 128;
    #pragma unroll
    for (int tm = 0; tm < 4; tm++) {
        #pragma unroll
        for (int tn = 0; tn < 4; tn++) {
            int mg = m0 + wm * 64 + tm * 16 + g2;
            int cg = n0 + wn * 32 + tn * 8 + q2;
            size_t o0 = (size_t)mg * Nt + cg;
            size_t o1 = o0 + 8 * Nt;
            float* a = acc[tm][tn];
            *(float2*)(C + o0) = make_float2(a[0], a[1]);
            *(float2*)(C + o1) = make_float2(a[2], a[3]);
        }
    }
}

// ---------------------------------------------------------------------------
extern "C" void kernel_launch(void* const* d_in, const int* in_sizes, int n_in,
                              void* d_out, int out_size)
{
    const float* x        = (const float*)d_in[0];
    const float* router_w = (const float*)d_in[1];
    const float* w1       = (const float*)d_in[2];
    const float* w2       = (const float*)d_in[3];
    const float* w3       = (const float*)d_in[4];
    const float* lora_A   = (const float*)d_in[5];
    const float* lora_B   = (const float*)d_in[6];
    float* out = (float*)d_out;

    static bool init_done = false;
    static __half *xh, *b1, *b3, *b2, *a2, *c16, *lbT;
    if (!init_done) {
        cudaGetSymbolAddress((void**)&xh,  g_xh);
        cudaGetSymbolAddress((void**)&b1,  g_b1);
        cudaGetSymbolAddress((void**)&b3,  g_b3);
        cudaGetSymbolAddress((void**)&b2,  g_b2);
        cudaGetSymbolAddress((void**)&a2,  g_a2);
        cudaGetSymbolAddress((void**)&c16, g_c16);
        cudaGetSymbolAddress((void**)&lbT, g_lbT);
        cudaFuncSetAttribute(gemm_gateup_kernel,
                             cudaFuncAttributeMaxDynamicSharedMemorySize, FUSED_SMEM);
        cudaFuncSetAttribute(gemm_down_kernel,
                             cudaFuncAttributeMaxDynamicSharedMemorySize, GEMM_SMEM);
        init_done = true;
    }

    float* logits_out = nullptr;
    if ((size_t)out_size >= (size_t)NTOK * HDIM + (size_t)NTOK * NEXP)
        logits_out = out + (size_t)NTOK * HDIM;

    // merged prep: 3 weight transposes + lora_B transpose + router/LoRA/x-convert
    prep_kernel<<<TRL_BLOCKS + NTOK, 256>>>(
        x, router_w, lora_A, lora_B, logits_out, w1, w3, w2, b1, b3, b2);

    // Fused gate+up: a2 = fp16(silu(x@w1) * (x@w3)), 128x64 tiles
    gemm_gateup_kernel<<<dim3(FDIM / 64, NTOK / 128), 256, FUSED_SMEM>>>(
        xh, b1, b3, a2, HDIM);

    // Down-proj + LoRA prefix: out = c16@lbT^T + a2@w2 (beta=0 store)
    gemm_down_kernel<<<dim3(HDIM / 128, NTOK / 128), 256, GEMM_SMEM>>>(
        a2, b2, c16, lbT, out, FDIM);
}

// round 15
// speedup vs baseline: 1.0302x; 1.0048x over previous
#include <cuda_runtime.h>
#include <cuda_fp16.h>
#include <cstdint>
#include <math.h>

#define NTOK 4096
#define HDIM 4096
#define FDIM 14336
#define NEXP 8
#define NR   8
#define LSCALE 2.0f

#define TR_BLOCKS  (3 * 28672)
#define TRL_BLOCKS (TR_BLOCKS + 128)   // + lora_B transpose

// ---------------------------------------------------------------------------
// Scratch (__device__ globals; allocation-free rule)
// ---------------------------------------------------------------------------
__device__ __half g_xh[(size_t)NTOK * HDIM];    // x as fp16 [N,H]
__device__ __half g_b1[(size_t)FDIM * HDIM];    // w1^T [F,H] fp16
__device__ __half g_b3[(size_t)FDIM * HDIM];    // w3^T [F,H] fp16
__device__ __half g_b2[(size_t)HDIM * FDIM];    // w2^T [H,F] fp16
__device__ __half g_a2[(size_t)NTOK * FDIM];    // silu(gate)*up fp16 [N,F]
__device__ __half g_c16[(size_t)NTOK * 64];     // LoRA coeffs fp16 [N,64]
__device__ __half g_lbT[(size_t)HDIM * 64];     // lora_B^T [H,64] fp16

// ---------------------------------------------------------------------------
// Asm helpers (sm_80-level features; legal on plain sm_103 target)
// ---------------------------------------------------------------------------
__device__ __forceinline__ uint32_t smem_u32(const void* p) {
    uint32_t a;
    asm("{ .reg .u64 t; cvta.to.shared.u64 t, %1; cvt.u32.u64 %0, t; }" : "=r"(a) : "l"(p));
    return a;
}

#define CP16(dst, src) \
    asm volatile("cp.async.cg.shared.global [%0], [%1], 16;" :: "r"(dst), "l"(src))
#define CP_COMMIT() asm volatile("cp.async.commit_group;" ::: "memory")
#define CP_WAIT1()  asm volatile("cp.async.wait_group 1;" ::: "memory")

#define LDSM4(r0, r1, r2, r3, a) \
    asm volatile("ldmatrix.sync.aligned.m8n8.x4.shared.b16 {%0,%1,%2,%3}, [%4];" \
        : "=r"(r0), "=r"(r1), "=r"(r2), "=r"(r3) : "r"(a))

#define MMA_F16(c, a0, a1, a2, a3, b0, b1) \
    asm volatile("mma.sync.aligned.m16n8k16.row.col.f32.f16.f16.f32 " \
        "{%0,%1,%2,%3}, {%4,%5,%6,%7}, {%8,%9}, {%0,%1,%2,%3};" \
        : "+f"((c)[0]), "+f"((c)[1]), "+f"((c)[2]), "+f"((c)[3]) \
        : "r"(a0), "r"(a1), "r"(a2), "r"(a3), "r"(b0), "r"(b1))

// ---------------------------------------------------------------------------
// MERGED prep kernel (1D grid), reg-capped to 32 for full occupancy:
//   bid < TR_BLOCKS      : w1/w3/w2 transpose+convert
//   bid < TRL_BLOCKS     : lora_B [64,4096] -> [4096,64] fp16
//   else                 : router + LoRA coeffs (fp16) + x fp16 conversion
// ---------------------------------------------------------------------------
#define PREP_SMEM_BYTES (HDIM * 4 + NEXP * NR * 4 + NEXP * 4 + 16)  // ~16.7 KB

__global__ void __launch_bounds__(256, 8) prep_kernel(
    const float* __restrict__ x, const float* __restrict__ router_w,
    const float* __restrict__ lora_A, const float* __restrict__ lora_B,
    float* __restrict__ logits_out,
    const float* __restrict__ w1, const float* __restrict__ w3,
    const float* __restrict__ w2,
    __half* __restrict__ b1, __half* __restrict__ b3, __half* __restrict__ b2)
{
    __shared__ __align__(16) char smraw[PREP_SMEM_BYTES];
    int bid = blockIdx.x;
    int tid = threadIdx.x;

    if (bid < TRL_BLOCKS) {
        // ---------------- transpose path (needs 8.5 KB of smraw) ----------------
        float (*t)[33] = reinterpret_cast<float(*)[33]>(smraw);
        int which = bid / 28672;        // 0,1,2 big weights; 3 = lora_B (128 blocks)
        int b     = bid % 28672;
        const float* W;
        __half* out;
        int K, N, nBlk;
        if (which == 0)      { W = w1;     out = b1;    K = HDIM; N = FDIM; nBlk = FDIM / 32; }
        else if (which == 1) { W = w3;     out = b3;    K = HDIM; N = FDIM; nBlk = FDIM / 32; }
        else if (which == 2) { W = w2;     out = b2;    K = FDIM; N = HDIM; nBlk = HDIM / 32; }
        else                 { W = lora_B; out = g_lbT; K = 64;   N = HDIM; nBlk = HDIM / 32; }

        int n0 = (b % nBlk) * 32;
        int k0 = (b / nBlk) * 64;
        int tx = tid & 31, ty = tid >> 5;   // 32 x 8
        #pragma unroll
        for (int j = 0; j < 8; j++)
            t[ty + 8 * j][tx] = W[(size_t)(k0 + ty + 8 * j) * N + n0 + tx];
        __syncthreads();
        #pragma unroll
        for (int j = 0; j < 4; j++) {
            int n = ty + 8 * j;
            __half2 h = __floats2half2_rn(t[2 * tx][n], t[2 * tx + 1][n]);
            *(__half2*)(out + (size_t)(n0 + n) * K + k0 + 2 * tx) = h;
        }
        return;
    }

    // ---------------- router path (256 threads) ----------------
    int n = bid - TRL_BLOCKS;
    float* xs  = (float*)smraw;                                 // HDIM floats
    float* red = (float*)(smraw + HDIM * 4);                    // [8 warps][NR]
    float* logits = red + NEXP * NR;
    int*   sel    = (int*)(logits + NEXP);
    float* rws    = (float*)(sel + 2);

    const float* xr = x + (size_t)n * HDIM;
    for (int i = tid; i < HDIM / 4; i += 256)
        ((float4*)xs)[i] = ((const float4*)xr)[i];
    __syncthreads();

    // fp16 conversion of x
    {
        __half* xo = g_xh + (size_t)n * HDIM;
        for (int i = tid; i < HDIM / 2; i += 256)
            *(__half2*)(xo + 2 * i) = __floats2half2_rn(xs[2 * i], xs[2 * i + 1]);
    }

    int wid = tid >> 5, lane = tid & 31;
    // logits: one expert per warp
    {
        int e = wid;
        const float* wr = router_w + (size_t)e * HDIM;
        float s = 0.f;
        for (int h = lane; h < HDIM; h += 32) s += xs[h] * wr[h];
        #pragma unroll
        for (int o = 16; o; o >>= 1) s += __shfl_down_sync(0xffffffffu, s, o);
        if (lane == 0) {
            logits[e] = s;
            if (logits_out) logits_out[(size_t)n * NEXP + e] = s;
        }
    }
    __syncthreads();

    if (tid == 0) {
        float m = -1e30f;
        for (int e = 0; e < NEXP; e++) m = fmaxf(m, logits[e]);
        float p[NEXP];
        for (int e = 0; e < NEXP; e++) p[e] = expf(logits[e] - m);
        int i0 = 0;
        for (int e = 1; e < NEXP; e++) if (p[e] > p[i0]) i0 = e;
        int i1 = -1;
        for (int e = 0; e < NEXP; e++) {
            if (e == i0) continue;
            if (i1 < 0 || p[e] > p[i1]) i1 = e;
        }
        float s2 = p[i0] + p[i1];
        sel[0] = i0; sel[1] = i1;
        rws[0] = p[i0] / s2; rws[1] = p[i1] / s2;
    }
    // zero fp16 coefficient row (64 halves = 32 half2)
    if (tid < 32) {
        __half2 z; z.x = __float2half(0.f); z.y = __float2half(0.f);
        ((__half2*)(g_c16 + (size_t)n * 64))[tid] = z;
    }
    __syncthreads();

    // coalesced LoRA-A projection: warp -> (expert slot k = wid>>2, h-quarter),
    // then in-warp shuffle reduction (smem-light)
    {
        int k = wid >> 2;                       // 0..1
        int q = wid & 3;                        // 0..3
        int e = sel[k];
        const float* A = lora_A + (size_t)e * HDIM * NR;
        float acc[NR];
        #pragma unroll
        for (int r = 0; r < NR; r++) acc[r] = 0.f;
        int h0 = q * (HDIM / 4);
        for (int it = 0; it < (HDIM / 4) / 32; it++) {
            int h = h0 + it * 32 + lane;
            const float4* ap = (const float4*)(A + (size_t)h * NR);
            float4 a0 = ap[0];
            float4 a1 = ap[1];
            float xv = xs[h];
            acc[0] += xv * a0.x; acc[1] += xv * a0.y;
            acc[2] += xv * a0.z; acc[3] += xv * a0.w;
            acc[4] += xv * a1.x; acc[5] += xv * a1.y;
            acc[6] += xv * a1.z; acc[7] += xv * a1.w;
        }
        #pragma unroll
        for (int r = 0; r < NR; r++) {
            #pragma unroll
            for (int o = 16; o; o >>= 1)
                acc[r] += __shfl_down_sync(0xffffffffu, acc[r], o);
        }
        if (lane == 0) {
            #pragma unroll
            for (int r = 0; r < NR; r++) red[wid * NR + r] = acc[r];
        }
    }
    __syncthreads();

    if (tid < 2 * NR) {
        int k = tid >> 3;
        int r = tid & 7;
        float s = red[(4 * k + 0) * NR + r] + red[(4 * k + 1) * NR + r]
                + red[(4 * k + 2) * NR + r] + red[(4 * k + 3) * NR + r];
        g_c16[(size_t)n * 64 + sel[k] * NR + r] = __float2half(rws[k] * LSCALE * s);
    }
}

// ---------------------------------------------------------------------------
// FUSED gate+up GEMM, 128m x 64n CTA tile (occ=2). (unchanged)
// ---------------------------------------------------------------------------
#define FSTG 32768
#define FUSED_SMEM (3 * FSTG)

__device__ __forceinline__ void issue_stage_gu(
    uint32_t st, const __half* A, const __half* B1, const __half* B3,
    int m0, int n0, int kpos, int K, int lr, int lkc)
{
    #pragma unroll
    for (int rr = 0; rr < 256; rr += 32) {
        int row = lr + rr;
        uint32_t so = row * 128 + ((lkc ^ (row & 7)) << 4);
        const __half* src;
        if (rr < 128)      src = A  + (size_t)(m0 + row) * K;
        else if (rr < 192) src = B1 + (size_t)(n0 + row - 128) * K;
        else               src = B3 + (size_t)(n0 + row - 192) * K;
        CP16(st + so, src + kpos + lkc * 8);
    }
    CP_COMMIT();
}

__global__ void __launch_bounds__(256, 2) gemm_gateup_kernel(
    const __half* __restrict__ A, const __half* __restrict__ B1,
    const __half* __restrict__ B3, __half* __restrict__ oA2, int K)
{
    extern __shared__ __align__(1024) char smem[];
    uint32_t sb = smem_u32(smem);
    int tid = threadIdx.x;
    int wid = tid >> 5, lane = tid & 31;
    int wm = wid >> 2, wn = wid & 3;

    int lin = blockIdx.y * gridDim.x + blockIdx.x;
    int gs  = 8 * gridDim.y;
    int g   = lin / gs, r = lin - g * gs;
    int m0  = (r >> 3) * 128;
    int n0  = (g * 8 + (r & 7)) * 64;

    int NT = K >> 6;
    int lr = tid >> 3, lkc = tid & 7;

    int laneM  = lane & 15;
    int kHalfA = lane >> 4;
    int aSw    = laneM & 7;
    uint32_t rowOffA[4];
    #pragma unroll
    for (int tm = 0; tm < 4; tm++)
        rowOffA[tm] = (uint32_t)(wm * 64 + tm * 16 + laneM) * 128;
    int l7     = lane & 7;
    int kHalfB = (lane >> 3) & 1;
    uint32_t rowB = (uint32_t)(wn * 16 + ((lane >> 4) & 1) * 8 + l7) * 128;

    float accG[4][2][4], accU[4][2][4];
    #pragma unroll
    for (int i = 0; i < 4; i++)
        #pragma unroll
        for (int j = 0; j < 2; j++)
            #pragma unroll
            for (int q = 0; q < 4; q++) { accG[i][j][q] = 0.f; accU[i][j][q] = 0.f; }

    issue_stage_gu(sb,        A, B1, B3, m0, n0, 0,  K, lr, lkc);
    issue_stage_gu(sb + FSTG, A, B1, B3, m0, n0, 64, K, lr, lkc);

    for (int kt = 0; kt < NT; kt++) {
        CP_WAIT1();
        __syncthreads();
        if (kt + 2 < NT)
            issue_stage_gu(sb + ((kt + 2) % 3) * FSTG, A, B1, B3,
                           m0, n0, (kt + 2) << 6, K, lr, lkc);
        else
            CP_COMMIT();

        uint32_t st = sb + (kt % 3) * FSTG;
        #pragma unroll
        for (int kk = 0; kk < 4; kk++) {
            uint32_t ah[4][4], b1f[4], b3f[4];
            uint32_t chA = (uint32_t)(((kk * 2 + kHalfA) ^ aSw) << 4);
            #pragma unroll
            for (int tm = 0; tm < 4; tm++)
                LDSM4(ah[tm][0], ah[tm][1], ah[tm][2], ah[tm][3], st + rowOffA[tm] + chA);
            uint32_t chB = (uint32_t)(((kk * 2 + kHalfB) ^ l7) << 4);
            LDSM4(b1f[0], b1f[1], b1f[2], b1f[3], st + 16384 + rowB + chB);
            LDSM4(b3f[0], b3f[1], b3f[2], b3f[3], st + 24576 + rowB + chB);
            #pragma unroll
            for (int tm = 0; tm < 4; tm++)
                #pragma unroll
                for (int tn = 0; tn < 2; tn++) {
                    MMA_F16(accG[tm][tn], ah[tm][0], ah[tm][1], ah[tm][2], ah[tm][3],
                            b1f[2 * tn], b1f[2 * tn + 1]);
                    MMA_F16(accU[tm][tn], ah[tm][0], ah[tm][1], ah[tm][2], ah[tm][3],
                            b3f[2 * tn], b3f[2 * tn + 1]);
                }
        }
    }

    int g2 = lane >> 2, q2 = (lane & 3) * 2;
    size_t Nt = (size_t)gridDim.x * 64;
    #pragma unroll
    for (int tm = 0; tm < 4; tm++) {
        #pragma unroll
        for (int tn = 0; tn < 2; tn++) {
            int mg = m0 + wm * 64 + tm * 16 + g2;
            int cg = n0 + wn * 16 + tn * 8 + q2;
            size_t o0 = (size_t)mg * Nt + cg;
            size_t o1 = o0 + 8 * Nt;
            float* gg = accG[tm][tn];
            float* uu = accU[tm][tn];
            float v0 = gg[0] / (1.f + __expf(-gg[0])) * uu[0];
            float v1 = gg[1] / (1.f + __expf(-gg[1])) * uu[1];
            float v2 = gg[2] / (1.f + __expf(-gg[2])) * uu[2];
            float v3 = gg[3] / (1.f + __expf(-gg[3])) * uu[3];
            *(__half2*)(oA2 + o0) = __floats2half2_rn(v0, v1);
            *(__half2*)(oA2 + o1) = __floats2half2_rn(v2, v3);
        }
    }
}

// ---------------------------------------------------------------------------
// Down-projection + LoRA fp16 GEMM (writes out, beta=0). (unchanged)
// ---------------------------------------------------------------------------
#define STAGE_BYTES 32768
#define GEMM_SMEM   (3 * STAGE_BYTES)

__device__ __forceinline__ void issue_stage_dn(
    uint32_t st, const __half* A, const __half* B,
    const __half* cA, const __half* cB,
    int m0, int n0, int ci, int K, int lr, int lkc)
{
    #pragma unroll
    for (int rr = 0; rr < 128; rr += 32) {
        int row = lr + rr;
        uint32_t so = row * 128 + ((lkc ^ (row & 7)) << 4);
        const __half* sA;
        const __half* sB;
        if (ci == 0) {
            sA = cA + (size_t)(m0 + row) * 64 + lkc * 8;
            sB = cB + (size_t)(n0 + row) * 64 + lkc * 8;
        } else {
            int kpos = (ci - 1) << 6;
            sA = A + (size_t)(m0 + row) * K + kpos + lkc * 8;
            sB = B + (size_t)(n0 + row) * K + kpos + lkc * 8;
        }
        CP16(st + so,         sA);
        CP16(st + 16384 + so, sB);
    }
    CP_COMMIT();
}

__global__ void __launch_bounds__(256, 2) gemm_down_kernel(
    const __half* __restrict__ A, const __half* __restrict__ B,
    const __half* __restrict__ cA, const __half* __restrict__ cB,
    float* __restrict__ C, int K)
{
    extern __shared__ __align__(1024) char smem[];
    uint32_t sb = smem_u32(smem);
    int tid = threadIdx.x;
    int wid = tid >> 5, lane = tid & 31;
    int wm = wid >> 2, wn = wid & 3;

    int lin = blockIdx.y * gridDim.x + blockIdx.x;
    int gs  = 8 * gridDim.y;
    int g   = lin / gs, r = lin - g * gs;
    int m0  = (r >> 3) * 128;
    int n0  = (g * 8 + (r & 7)) * 128;

    int NCH = (K >> 6) + 1;
    int lr = tid >> 3, lkc = tid & 7;

    int laneM  = lane & 15;
    int kHalfA = lane >> 4;
    int aSw    = laneM & 7;
    uint32_t rowOffA[4];
    #pragma unroll
    for (int tm = 0; tm < 4; tm++)
        rowOffA[tm] = (uint32_t)(wm * 64 + tm * 16 + laneM) * 128;
    int l7     = lane & 7;
    int kHalfB = (lane >> 3) & 1;
    uint32_t rowOffB[2];
    #pragma unroll
    for (int pr = 0; pr < 2; pr++)
        rowOffB[pr] = (uint32_t)(wn * 32 + pr * 16 + ((lane >> 4) & 1) * 8 + l7) * 128;

    float acc[4][4][4];
    #pragma unroll
    for (int i = 0; i < 4; i++)
        #pragma unroll
        for (int j = 0; j < 4; j++)
            #pragma unroll
            for (int q = 0; q < 4; q++) acc[i][j][q] = 0.f;

    issue_stage_dn(sb,               A, B, cA, cB, m0, n0, 0, K, lr, lkc);
    issue_stage_dn(sb + STAGE_BYTES, A, B, cA, cB, m0, n0, 1, K, lr, lkc);

    for (int ci = 0; ci < NCH; ci++) {
        CP_WAIT1();
        __syncthreads();
        if (ci + 2 < NCH)
            issue_stage_dn(sb + ((ci + 2) % 3) * STAGE_BYTES, A, B, cA, cB,
                           m0, n0, ci + 2, K, lr, lkc);
        else
            CP_COMMIT();

        uint32_t st = sb + (ci % 3) * STAGE_BYTES;
        #pragma unroll
        for (int kk = 0; kk < 4; kk++) {
            uint32_t ah[4][4], bh[8];
            uint32_t chA = (uint32_t)(((kk * 2 + kHalfA) ^ aSw) << 4);
            #pragma unroll
            for (int tm = 0; tm < 4; tm++)
                LDSM4(ah[tm][0], ah[tm][1], ah[tm][2], ah[tm][3], st + rowOffA[tm] + chA);
            uint32_t chB = (uint32_t)(((kk * 2 + kHalfB) ^ l7) << 4);
            LDSM4(bh[0], bh[1], bh[2], bh[3], st + 16384 + rowOffB[0] + chB);
            LDSM4(bh[4], bh[5], bh[6], bh[7], st + 16384 + rowOffB[1] + chB);
            #pragma unroll
            for (int tm = 0; tm < 4; tm++)
                #pragma unroll
                for (int tn = 0; tn < 4; tn++)
                    MMA_F16(acc[tm][tn], ah[tm][0], ah[tm][1], ah[tm][2], ah[tm][3],
                            bh[2 * tn], bh[2 * tn + 1]);
        }
    }

    int g2 = lane >> 2, q2 = (lane & 3) * 2;
    size_t Nt = (size_t)gridDim.x * 128;
    #pragma unroll
    for (int tm = 0; tm < 4; tm++) {
        #pragma unroll
        for (int tn = 0; tn < 4; tn++) {
            int mg = m0 + wm * 64 + tm * 16 + g2;
            int cg = n0 + wn * 32 + tn * 8 + q2;
            size_t o0 = (size_t)mg * Nt + cg;
            size_t o1 = o0 + 8 * Nt;
            float* a = acc[tm][tn];
            *(float2*)(C + o0) = make_float2(a[0], a[1]);
            *(float2*)(C + o1) = make_float2(a[2], a[3]);
        }
    }
}

// ---------------------------------------------------------------------------
extern "C" void kernel_launch(void* const* d_in, const int* in_sizes, int n_in,
                              void* d_out, int out_size)
{
    const float* x        = (const float*)d_in[0];
    const float* router_w = (const float*)d_in[1];
    const float* w1       = (const float*)d_in[2];
    const float* w2       = (const float*)d_in[3];
    const float* w3       = (const float*)d_in[4];
    const float* lora_A   = (const float*)d_in[5];
    const float* lora_B   = (const float*)d_in[6];
    float* out = (float*)d_out;

    static bool init_done = false;
    static __half *xh, *b1, *b3, *b2, *a2, *c16, *lbT;
    if (!init_done) {
        cudaGetSymbolAddress((void**)&xh,  g_xh);
        cudaGetSymbolAddress((void**)&b1,  g_b1);
        cudaGetSymbolAddress((void**)&b3,  g_b3);
        cudaGetSymbolAddress((void**)&b2,  g_b2);
        cudaGetSymbolAddress((void**)&a2,  g_a2);
        cudaGetSymbolAddress((void**)&c16, g_c16);
        cudaGetSymbolAddress((void**)&lbT, g_lbT);
        cudaFuncSetAttribute(gemm_gateup_kernel,
                             cudaFuncAttributeMaxDynamicSharedMemorySize, FUSED_SMEM);
        cudaFuncSetAttribute(gemm_down_kernel,
                             cudaFuncAttributeMaxDynamicSharedMemorySize, GEMM_SMEM);
        init_done = true;
    }

    float* logits_out = nullptr;
    if ((size_t)out_size >= (size_t)NTOK * HDIM + (size_t)NTOK * NEXP)
        logits_out = out + (size_t)NTOK * HDIM;

    // merged prep: 3 weight transposes + lora_B transpose + router/LoRA/x-convert
    prep_kernel<<<TRL_BLOCKS + NTOK, 256>>>(
        x, router_w, lora_A, lora_B, logits_out, w1, w3, w2, b1, b3, b2);

    // Fused gate+up: a2 = fp16(silu(x@w1) * (x@w3)), 128x64 tiles
    gemm_gateup_kernel<<<dim3(FDIM / 64, NTOK / 128), 256, FUSED_SMEM>>>(
        xh, b1, b3, a2, HDIM);

    // Down-proj + LoRA prefix: out = c16@lbT^T + a2@w2 (beta=0 store)
    gemm_down_kernel<<<dim3(HDIM / 128, NTOK / 128), 256, GEMM_SMEM>>>(
        a2, b2, c16, lbT, out, FDIM);
}

// round 16
// speedup vs baseline: 1.0314x; 1.0011x over previous
#include <cuda_runtime.h>
#include <cuda_fp16.h>
#include <cstdint>
#include <math.h>

#define NTOK 4096
#define HDIM 4096
#define FDIM 14336
#define NEXP 8
#define NR   8
#define LSCALE 2.0f

#define TR_BLOCKS  (3 * 28672)
#define TRL_BLOCKS (TR_BLOCKS + 128)   // + lora_B transpose

// ---------------------------------------------------------------------------
// Scratch (__device__ globals; allocation-free rule)
// ---------------------------------------------------------------------------
__device__ __half g_xh[(size_t)NTOK * HDIM];    // x as fp16 [N,H]
__device__ __half g_b1[(size_t)FDIM * HDIM];    // w1^T [F,H] fp16
__device__ __half g_b3[(size_t)FDIM * HDIM];    // w3^T [F,H] fp16
__device__ __half g_b2[(size_t)HDIM * FDIM];    // w2^T [H,F] fp16
__device__ __half g_a2[(size_t)NTOK * FDIM];    // silu(gate)*up fp16 [N,F]
__device__ __half g_c16[(size_t)NTOK * 64];     // LoRA coeffs fp16 [N,64]
__device__ __half g_lbT[(size_t)HDIM * 64];     // lora_B^T [H,64] fp16

// ---------------------------------------------------------------------------
// Asm helpers (sm_80-level features; legal on plain sm_103 target)
// ---------------------------------------------------------------------------
__device__ __forceinline__ uint32_t smem_u32(const void* p) {
    uint32_t a;
    asm("{ .reg .u64 t; cvta.to.shared.u64 t, %1; cvt.u32.u64 %0, t; }" : "=r"(a) : "l"(p));
    return a;
}

#define CP16(dst, src) \
    asm volatile("cp.async.cg.shared.global [%0], [%1], 16;" :: "r"(dst), "l"(src))
#define CP_COMMIT() asm volatile("cp.async.commit_group;" ::: "memory")
#define CP_WAIT1()  asm volatile("cp.async.wait_group 1;" ::: "memory")

#define LDSM4(r0, r1, r2, r3, a) \
    asm volatile("ldmatrix.sync.aligned.m8n8.x4.shared.b16 {%0,%1,%2,%3}, [%4];" \
        : "=r"(r0), "=r"(r1), "=r"(r2), "=r"(r3) : "r"(a))

#define MMA_F16(c, a0, a1, a2, a3, b0, b1) \
    asm volatile("mma.sync.aligned.m16n8k16.row.col.f32.f16.f16.f32 " \
        "{%0,%1,%2,%3}, {%4,%5,%6,%7}, {%8,%9}, {%0,%1,%2,%3};" \
        : "+f"((c)[0]), "+f"((c)[1]), "+f"((c)[2]), "+f"((c)[3]) \
        : "r"(a0), "r"(a1), "r"(a2), "r"(a3), "r"(b0), "r"(b1))

// ---------------------------------------------------------------------------
// MERGED prep kernel (1D grid), reg-capped to 32 for full occupancy:
//   bid < TR_BLOCKS      : w1/w3/w2 transpose+convert (vectorized 16B LDG/STG)
//   bid < TRL_BLOCKS     : lora_B [64,4096] -> [4096,64] fp16
//   else                 : router + LoRA coeffs (fp16) + x fp16 conversion
// ---------------------------------------------------------------------------
#define PREP_SMEM_BYTES (HDIM * 4 + NEXP * NR * 4 + NEXP * 4 + 16)  // ~16.7 KB

__global__ void __launch_bounds__(256, 8) prep_kernel(
    const float* __restrict__ x, const float* __restrict__ router_w,
    const float* __restrict__ lora_A, const float* __restrict__ lora_B,
    float* __restrict__ logits_out,
    const float* __restrict__ w1, const float* __restrict__ w3,
    const float* __restrict__ w2,
    __half* __restrict__ b1, __half* __restrict__ b3, __half* __restrict__ b2)
{
    __shared__ __align__(16) char smraw[PREP_SMEM_BYTES];
    int bid = blockIdx.x;
    int tid = threadIdx.x;

    if (bid < TRL_BLOCKS) {
        // ---------------- transpose path (tile 32n x 64k, vectorized) --------
        float (*t)[33] = reinterpret_cast<float(*)[33]>(smraw);
        int which = bid / 28672;        // 0,1,2 big weights; 3 = lora_B (128 blocks)
        int b     = bid % 28672;
        const float* W;
        __half* out;
        int K, N, nBlk;
        if (which == 0)      { W = w1;     out = b1;    K = HDIM; N = FDIM; nBlk = FDIM / 32; }
        else if (which == 1) { W = w3;     out = b3;    K = HDIM; N = FDIM; nBlk = FDIM / 32; }
        else if (which == 2) { W = w2;     out = b2;    K = FDIM; N = HDIM; nBlk = HDIM / 32; }
        else                 { W = lora_B; out = g_lbT; K = 64;   N = HDIM; nBlk = HDIM / 32; }

        int n0 = (b % nBlk) * 32;
        int k0 = (b / nBlk) * 64;

        // Load: thread -> (k-row = tid>>3 (+32), 4 n-cols = (tid&7)*4), float4 LDG
        {
            int row = tid >> 3;          // 0..31
            int c4  = (tid & 7) * 4;     // 0,4,...,28
            #pragma unroll
            for (int rr = 0; rr < 64; rr += 32) {
                float4 v = *(const float4*)(W + (size_t)(k0 + row + rr) * N + n0 + c4);
                t[row + rr][c4 + 0] = v.x;
                t[row + rr][c4 + 1] = v.y;
                t[row + rr][c4 + 2] = v.z;
                t[row + rr][c4 + 3] = v.w;
            }
        }
        __syncthreads();
        // Store: thread -> (n-row = tid>>3, 8 k-vals = (tid&7)*8), STG.128
        {
            int n = tid >> 3;            // 0..31
            int c = tid & 7;             // 0..7 -> k offset 8c
            __half hv[8];
            #pragma unroll
            for (int j = 0; j < 8; j++)
                hv[j] = __float2half_rn(t[8 * c + j][n]);
            *(uint4*)(out + (size_t)(n0 + n) * K + k0 + 8 * c) = *(uint4*)hv;
        }
        return;
    }

    // ---------------- router path (256 threads) ----------------
    int n = bid - TRL_BLOCKS;
    float* xs  = (float*)smraw;                                 // HDIM floats
    float* red = (float*)(smraw + HDIM * 4);                    // [8 warps][NR]
    float* logits = red + NEXP * NR;
    int*   sel    = (int*)(logits + NEXP);
    float* rws    = (float*)(sel + 2);

    const float* xr = x + (size_t)n * HDIM;
    for (int i = tid; i < HDIM / 4; i += 256)
        ((float4*)xs)[i] = ((const float4*)xr)[i];
    __syncthreads();

    // fp16 conversion of x
    {
        __half* xo = g_xh + (size_t)n * HDIM;
        for (int i = tid; i < HDIM / 2; i += 256)
            *(__half2*)(xo + 2 * i) = __floats2half2_rn(xs[2 * i], xs[2 * i + 1]);
    }

    int wid = tid >> 5, lane = tid & 31;
    // logits: one expert per warp
    {
        int e = wid;
        const float* wr = router_w + (size_t)e * HDIM;
        float s = 0.f;
        for (int h = lane; h < HDIM; h += 32) s += xs[h] * wr[h];
        #pragma unroll
        for (int o = 16; o; o >>= 1) s += __shfl_down_sync(0xffffffffu, s, o);
        if (lane == 0) {
            logits[e] = s;
            if (logits_out) logits_out[(size_t)n * NEXP + e] = s;
        }
    }
    __syncthreads();

    if (tid == 0) {
        float m = -1e30f;
        for (int e = 0; e < NEXP; e++) m = fmaxf(m, logits[e]);
        float p[NEXP];
        for (int e = 0; e < NEXP; e++) p[e] = expf(logits[e] - m);
        int i0 = 0;
        for (int e = 1; e < NEXP; e++) if (p[e] > p[i0]) i0 = e;
        int i1 = -1;
        for (int e = 0; e < NEXP; e++) {
            if (e == i0) continue;
            if (i1 < 0 || p[e] > p[i1]) i1 = e;
        }
        float s2 = p[i0] + p[i1];
        sel[0] = i0; sel[1] = i1;
        rws[0] = p[i0] / s2; rws[1] = p[i1] / s2;
    }
    // zero fp16 coefficient row (64 halves = 32 half2)
    if (tid < 32) {
        __half2 z; z.x = __float2half(0.f); z.y = __float2half(0.f);
        ((__half2*)(g_c16 + (size_t)n * 64))[tid] = z;
    }
    __syncthreads();

    // coalesced LoRA-A projection: warp -> (expert slot k = wid>>2, h-quarter),
    // then in-warp shuffle reduction
    {
        int k = wid >> 2;                       // 0..1
        int q = wid & 3;                        // 0..3
        int e = sel[k];
        const float* A = lora_A + (size_t)e * HDIM * NR;
        float acc[NR];
        #pragma unroll
        for (int r = 0; r < NR; r++) acc[r] = 0.f;
        int h0 = q * (HDIM / 4);
        for (int it = 0; it < (HDIM / 4) / 32; it++) {
            int h = h0 + it * 32 + lane;
            const float4* ap = (const float4*)(A + (size_t)h * NR);
            float4 a0 = ap[0];
            float4 a1 = ap[1];
            float xv = xs[h];
            acc[0] += xv * a0.x; acc[1] += xv * a0.y;
            acc[2] += xv * a0.z; acc[3] += xv * a0.w;
            acc[4] += xv * a1.x; acc[5] += xv * a1.y;
            acc[6] += xv * a1.z; acc[7] += xv * a1.w;
        }
        #pragma unroll
        for (int r = 0; r < NR; r++) {
            #pragma unroll
            for (int o = 16; o; o >>= 1)
                acc[r] += __shfl_down_sync(0xffffffffu, acc[r], o);
        }
        if (lane == 0) {
            #pragma unroll
            for (int r = 0; r < NR; r++) red[wid * NR + r] = acc[r];
        }
    }
    __syncthreads();

    if (tid < 2 * NR) {
        int k = tid >> 3;
        int r = tid & 7;
        float s = red[(4 * k + 0) * NR + r] + red[(4 * k + 1) * NR + r]
                + red[(4 * k + 2) * NR + r] + red[(4 * k + 3) * NR + r];
        g_c16[(size_t)n * 64 + sel[k] * NR + r] = __float2half(rws[k] * LSCALE * s);
    }
}

// ---------------------------------------------------------------------------
// FUSED gate+up GEMM, 128m x 64n CTA tile (occ=2). (unchanged)
// ---------------------------------------------------------------------------
#define FSTG 32768
#define FUSED_SMEM (3 * FSTG)

__device__ __forceinline__ void issue_stage_gu(
    uint32_t st, const __half* A, const __half* B1, const __half* B3,
    int m0, int n0, int kpos, int K, int lr, int lkc)
{
    #pragma unroll
    for (int rr = 0; rr < 256; rr += 32) {
        int row = lr + rr;
        uint32_t so = row * 128 + ((lkc ^ (row & 7)) << 4);
        const __half* src;
        if (rr < 128)      src = A  + (size_t)(m0 + row) * K;
        else if (rr < 192) src = B1 + (size_t)(n0 + row - 128) * K;
        else               src = B3 + (size_t)(n0 + row - 192) * K;
        CP16(st + so, src + kpos + lkc * 8);
    }
    CP_COMMIT();
}

__global__ void __launch_bounds__(256, 2) gemm_gateup_kernel(
    const __half* __restrict__ A, const __half* __restrict__ B1,
    const __half* __restrict__ B3, __half* __restrict__ oA2, int K)
{
    extern __shared__ __align__(1024) char smem[];
    uint32_t sb = smem_u32(smem);
    int tid = threadIdx.x;
    int wid = tid >> 5, lane = tid & 31;
    int wm = wid >> 2, wn = wid & 3;

    int lin = blockIdx.y * gridDim.x + blockIdx.x;
    int gs  = 8 * gridDim.y;
    int g   = lin / gs, r = lin - g * gs;
    int m0  = (r >> 3) * 128;
    int n0  = (g * 8 + (r & 7)) * 64;

    int NT = K >> 6;
    int lr = tid >> 3, lkc = tid & 7;

    int laneM  = lane & 15;
    int kHalfA = lane >> 4;
    int aSw    = laneM & 7;
    uint32_t rowOffA[4];
    #pragma unroll
    for (int tm = 0; tm < 4; tm++)
        rowOffA[tm] = (uint32_t)(wm * 64 + tm * 16 + laneM) * 128;
    int l7     = lane & 7;
    int kHalfB = (lane >> 3) & 1;
    uint32_t rowB = (uint32_t)(wn * 16 + ((lane >> 4) & 1) * 8 + l7) * 128;

    float accG[4][2][4], accU[4][2][4];
    #pragma unroll
    for (int i = 0; i < 4; i++)
        #pragma unroll
        for (int j = 0; j < 2; j++)
            #pragma unroll
            for (int q = 0; q < 4; q++) { accG[i][j][q] = 0.f; accU[i][j][q] = 0.f; }

    issue_stage_gu(sb,        A, B1, B3, m0, n0, 0,  K, lr, lkc);
    issue_stage_gu(sb + FSTG, A, B1, B3, m0, n0, 64, K, lr, lkc);

    for (int kt = 0; kt < NT; kt++) {
        CP_WAIT1();
        __syncthreads();
        if (kt + 2 < NT)
            issue_stage_gu(sb + ((kt + 2) % 3) * FSTG, A, B1, B3,
                           m0, n0, (kt + 2) << 6, K, lr, lkc);
        else
            CP_COMMIT();

        uint32_t st = sb + (kt % 3) * FSTG;
        #pragma unroll
        for (int kk = 0; kk < 4; kk++) {
            uint32_t ah[4][4], b1f[4], b3f[4];
            uint32_t chA = (uint32_t)(((kk * 2 + kHalfA) ^ aSw) << 4);
            #pragma unroll
            for (int tm = 0; tm < 4; tm++)
                LDSM4(ah[tm][0], ah[tm][1], ah[tm][2], ah[tm][3], st + rowOffA[tm] + chA);
            uint32_t chB = (uint32_t)(((kk * 2 + kHalfB) ^ l7) << 4);
            LDSM4(b1f[0], b1f[1], b1f[2], b1f[3], st + 16384 + rowB + chB);
            LDSM4(b3f[0], b3f[1], b3f[2], b3f[3], st + 24576 + rowB + chB);
            #pragma unroll
            for (int tm = 0; tm < 4; tm++)
                #pragma unroll
                for (int tn = 0; tn < 2; tn++) {
                    MMA_F16(accG[tm][tn], ah[tm][0], ah[tm][1], ah[tm][2], ah[tm][3],
                            b1f[2 * tn], b1f[2 * tn + 1]);
                    MMA_F16(accU[tm][tn], ah[tm][0], ah[tm][1], ah[tm][2], ah[tm][3],
                            b3f[2 * tn], b3f[2 * tn + 1]);
                }
        }
    }

    int g2 = lane >> 2, q2 = (lane & 3) * 2;
    size_t Nt = (size_t)gridDim.x * 64;
    #pragma unroll
    for (int tm = 0; tm < 4; tm++) {
        #pragma unroll
        for (int tn = 0; tn < 2; tn++) {
            int mg = m0 + wm * 64 + tm * 16 + g2;
            int cg = n0 + wn * 16 + tn * 8 + q2;
            size_t o0 = (size_t)mg * Nt + cg;
            size_t o1 = o0 + 8 * Nt;
            float* gg = accG[tm][tn];
            float* uu = accU[tm][tn];
            float v0 = gg[0] / (1.f + __expf(-gg[0])) * uu[0];
            float v1 = gg[1] / (1.f + __expf(-gg[1])) * uu[1];
            float v2 = gg[2] / (1.f + __expf(-gg[2])) * uu[2];
            float v3 = gg[3] / (1.f + __expf(-gg[3])) * uu[3];
            *(__half2*)(oA2 + o0) = __floats2half2_rn(v0, v1);
            *(__half2*)(oA2 + o1) = __floats2half2_rn(v2, v3);
        }
    }
}

// ---------------------------------------------------------------------------
// Down-projection + LoRA fp16 GEMM (writes out, beta=0). (unchanged)
// ---------------------------------------------------------------------------
#define STAGE_BYTES 32768
#define GEMM_SMEM   (3 * STAGE_BYTES)

__device__ __forceinline__ void issue_stage_dn(
    uint32_t st, const __half* A, const __half* B,
    const __half* cA, const __half* cB,
    int m0, int n0, int ci, int K, int lr, int lkc)
{
    #pragma unroll
    for (int rr = 0; rr < 128; rr += 32) {
        int row = lr + rr;
        uint32_t so = row * 128 + ((lkc ^ (row & 7)) << 4);
        const __half* sA;
        const __half* sB;
        if (ci == 0) {
            sA = cA + (size_t)(m0 + row) * 64 + lkc * 8;
            sB = cB + (size_t)(n0 + row) * 64 + lkc * 8;
        } else {
            int kpos = (ci - 1) << 6;
            sA = A + (size_t)(m0 + row) * K + kpos + lkc * 8;
            sB = B + (size_t)(n0 + row) * K + kpos + lkc * 8;
        }
        CP16(st + so,         sA);
        CP16(st + 16384 + so, sB);
    }
    CP_COMMIT();
}

__global__ void __launch_bounds__(256, 2) gemm_down_kernel(
    const __half* __restrict__ A, const __half* __restrict__ B,
    const __half* __restrict__ cA, const __half* __restrict__ cB,
    float* __restrict__ C, int K)
{
    extern __shared__ __align__(1024) char smem[];
    uint32_t sb = smem_u32(smem);
    int tid = threadIdx.x;
    int wid = tid >> 5, lane = tid & 31;
    int wm = wid >> 2, wn = wid & 3;

    int lin = blockIdx.y * gridDim.x + blockIdx.x;
    int gs  = 8 * gridDim.y;
    int g   = lin / gs, r = lin - g * gs;
    int m0  = (r >> 3) * 128;
    int n0  = (g * 8 + (r & 7)) * 128;

    int NCH = (K >> 6) + 1;
    int lr = tid >> 3, lkc = tid & 7;

    int laneM  = lane & 15;
    int kHalfA = lane >> 4;
    int aSw    = laneM & 7;
    uint32_t rowOffA[4];
    #pragma unroll
    for (int tm = 0; tm < 4; tm++)
        rowOffA[tm] = (uint32_t)(wm * 64 + tm * 16 + laneM) * 128;
    int l7     = lane & 7;
    int kHalfB = (lane >> 3) & 1;
    uint32_t rowOffB[2];
    #pragma unroll
    for (int pr = 0; pr < 2; pr++)
        rowOffB[pr] = (uint32_t)(wn * 32 + pr * 16 + ((lane >> 4) & 1) * 8 + l7) * 128;

    float acc[4][4][4];
    #pragma unroll
    for (int i = 0; i < 4; i++)
        #pragma unroll
        for (int j = 0; j < 4; j++)
            #pragma unroll
            for (int q = 0; q < 4; q++) acc[i][j][q] = 0.f;

    issue_stage_dn(sb,               A, B, cA, cB, m0, n0, 0, K, lr, lkc);
    issue_stage_dn(sb + STAGE_BYTES, A, B, cA, cB, m0, n0, 1, K, lr, lkc);

    for (int ci = 0; ci < NCH; ci++) {
        CP_WAIT1();
        __syncthreads();
        if (ci + 2 < NCH)
            issue_stage_dn(sb + ((ci + 2) % 3) * STAGE_BYTES, A, B, cA, cB,
                           m0, n0, ci + 2, K, lr, lkc);
        else
            CP_COMMIT();

        uint32_t st = sb + (ci % 3) * STAGE_BYTES;
        #pragma unroll
        for (int kk = 0; kk < 4; kk++) {
            uint32_t ah[4][4], bh[8];
            uint32_t chA = (uint32_t)(((kk * 2 + kHalfA) ^ aSw) << 4);
            #pragma unroll
            for (int tm = 0; tm < 4; tm++)
                LDSM4(ah[tm][0], ah[tm][1], ah[tm][2], ah[tm][3], st + rowOffA[tm] + chA);
            uint32_t chB = (uint32_t)(((kk * 2 + kHalfB) ^ l7) << 4);
            LDSM4(bh[0], bh[1], bh[2], bh[3], st + 16384 + rowOffB[0] + chB);
            LDSM4(bh[4], bh[5], bh[6], bh[7], st + 16384 + rowOffB[1] + chB);
            #pragma unroll
            for (int tm = 0; tm < 4; tm++)
                #pragma unroll
                for (int tn = 0; tn < 4; tn++)
                    MMA_F16(acc[tm][tn], ah[tm][0], ah[tm][1], ah[tm][2], ah[tm][3],
                            bh[2 * tn], bh[2 * tn + 1]);
        }
    }

    int g2 = lane >> 2, q2 = (lane & 3) * 2;
    size_t Nt = (size_t)gridDim.x * 128;
    #pragma unroll
    for (int tm = 0; tm < 4; tm++) {
        #pragma unroll
        for (int tn = 0; tn < 4; tn++) {
            int mg = m0 + wm * 64 + tm * 16 + g2;
            int cg = n0 + wn * 32 + tn * 8 + q2;
            size_t o0 = (size_t)mg * Nt + cg;
            size_t o1 = o0 + 8 * Nt;
            float* a = acc[tm][tn];
            *(float2*)(C + o0) = make_float2(a[0], a[1]);
            *(float2*)(C + o1) = make_float2(a[2], a[3]);
        }
    }
}

// ---------------------------------------------------------------------------
extern "C" void kernel_launch(void* const* d_in, const int* in_sizes, int n_in,
                              void* d_out, int out_size)
{
    const float* x        = (const float*)d_in[0];
    const float* router_w = (const float*)d_in[1];
    const float* w1       = (const float*)d_in[2];
    const float* w2       = (const float*)d_in[3];
    const float* w3       = (const float*)d_in[4];
    const float* lora_A   = (const float*)d_in[5];
    const float* lora_B   = (const float*)d_in[6];
    float* out = (float*)d_out;

    static bool init_done = false;
    static __half *xh, *b1, *b3, *b2, *a2, *c16, *lbT;
    if (!init_done) {
        cudaGetSymbolAddress((void**)&xh,  g_xh);
        cudaGetSymbolAddress((void**)&b1,  g_b1);
        cudaGetSymbolAddress((void**)&b3,  g_b3);
        cudaGetSymbolAddress((void**)&b2,  g_b2);
        cudaGetSymbolAddress((void**)&a2,  g_a2);
        cudaGetSymbolAddress((void**)&c16, g_c16);
        cudaGetSymbolAddress((void**)&lbT, g_lbT);
        cudaFuncSetAttribute(gemm_gateup_kernel,
                             cudaFuncAttributeMaxDynamicSharedMemorySize, FUSED_SMEM);
        cudaFuncSetAttribute(gemm_down_kernel,
                             cudaFuncAttributeMaxDynamicSharedMemorySize, GEMM_SMEM);
        init_done = true;
    }

    float* logits_out = nullptr;
    if ((size_t)out_size >= (size_t)NTOK * HDIM + (size_t)NTOK * NEXP)
        logits_out = out + (size_t)NTOK * HDIM;

    // merged prep: 3 weight transposes + lora_B transpose + router/LoRA/x-convert
    prep_kernel<<<TRL_BLOCKS + NTOK, 256>>>(
        x, router_w, lora_A, lora_B, logits_out, w1, w3, w2, b1, b3, b2);

    // Fused gate+up: a2 = fp16(silu(x@w1) * (x@w3)), 128x64 tiles
    gemm_gateup_kernel<<<dim3(FDIM / 64, NTOK / 128), 256, FUSED_SMEM>>>(
        xh, b1, b3, a2, HDIM);

    // Down-proj + LoRA prefix: out = c16@lbT^T + a2@w2 (beta=0 store)
    gemm_down_kernel<<<dim3(HDIM / 128, NTOK / 128), 256, GEMM_SMEM>>>(
        a2, b2, c16, lbT, out, FDIM);
}

// round 17
// speedup vs baseline: 1.0594x; 1.0271x over previous
#include <cuda_runtime.h>
#include <cuda_fp16.h>
#include <cstdint>
#include <math.h>

#define NTOK 4096
#define HDIM 4096
#define FDIM 14336
#define NEXP 8
#define NR   8
#define LSCALE 2.0f

#define TR_BLOCKS  (3 * 28672)
#define TRL_BLOCKS (TR_BLOCKS + 128 + 128)   // + lora_B transpose + lora_A transpose

// ---------------------------------------------------------------------------
// Scratch (__device__ globals; allocation-free rule)
// ---------------------------------------------------------------------------
__device__ __half g_xh[(size_t)NTOK * HDIM];    // x as fp16 [N,H]
__device__ __half g_b1[(size_t)FDIM * HDIM];    // w1^T [F,H] fp16
__device__ __half g_b3[(size_t)FDIM * HDIM];    // w3^T [F,H] fp16
__device__ __half g_b2[(size_t)HDIM * FDIM];    // w2^T [H,F] fp16
__device__ __half g_a2[(size_t)NTOK * FDIM];    // silu(gate)*up fp16 [N,F]
__device__ __half g_c16[(size_t)NTOK * 64];     // masked LoRA coeffs fp16 [N,64]
__device__ __half g_lbT[(size_t)HDIM * 64];     // lora_B^T [H,64] fp16
__device__ __half g_laT[(size_t)64 * HDIM];     // lora_A all-expert^T [64,H] fp16
__device__ float  g_rw8[NTOK * NEXP];           // masked routing weights * LSCALE

// ---------------------------------------------------------------------------
// Asm helpers (sm_80-level features; legal on plain sm_103 target)
// ---------------------------------------------------------------------------
__device__ __forceinline__ uint32_t smem_u32(const void* p) {
    uint32_t a;
    asm("{ .reg .u64 t; cvta.to.shared.u64 t, %1; cvt.u32.u64 %0, t; }" : "=r"(a) : "l"(p));
    return a;
}

#define CP16(dst, src) \
    asm volatile("cp.async.cg.shared.global [%0], [%1], 16;" :: "r"(dst), "l"(src))
#define CP_COMMIT() asm volatile("cp.async.commit_group;" ::: "memory")
#define CP_WAIT1()  asm volatile("cp.async.wait_group 1;" ::: "memory")

#define LDSM4(r0, r1, r2, r3, a) \
    asm volatile("ldmatrix.sync.aligned.m8n8.x4.shared.b16 {%0,%1,%2,%3}, [%4];" \
        : "=r"(r0), "=r"(r1), "=r"(r2), "=r"(r3) : "r"(a))

#define MMA_F16(c, a0, a1, a2, a3, b0, b1) \
    asm volatile("mma.sync.aligned.m16n8k16.row.col.f32.f16.f16.f32 " \
        "{%0,%1,%2,%3}, {%4,%5,%6,%7}, {%8,%9}, {%0,%1,%2,%3};" \
        : "+f"((c)[0]), "+f"((c)[1]), "+f"((c)[2]), "+f"((c)[3]) \
        : "r"(a0), "r"(a1), "r"(a2), "r"(a3), "r"(b0), "r"(b1))

// ---------------------------------------------------------------------------
// MERGED prep kernel (1D grid), reg-capped to 32:
//   bid < TR_BLOCKS         : w1/w3/w2 transpose+convert (16B LDG/STG)
//   bid < TR_BLOCKS+128     : lora_B [64,H] -> lbT [H,64] fp16
//   bid < TRL_BLOCKS        : lora_A [E,H,R] -> laT [64,H] fp16
//   else                    : router (logits + masked weights) + x fp16 convert
// ---------------------------------------------------------------------------
#define PREP_SMEM_BYTES (HDIM * 4 + NEXP * 4 + 16)

__global__ void __launch_bounds__(256, 8) prep_kernel(
    const float* __restrict__ x, const float* __restrict__ router_w,
    const float* __restrict__ lora_A, const float* __restrict__ lora_B,
    float* __restrict__ logits_out,
    const float* __restrict__ w1, const float* __restrict__ w3,
    const float* __restrict__ w2,
    __half* __restrict__ b1, __half* __restrict__ b3, __half* __restrict__ b2)
{
    __shared__ __align__(16) char smraw[PREP_SMEM_BYTES];
    int bid = blockIdx.x;
    int tid = threadIdx.x;

    if (bid < TR_BLOCKS + 128) {
        // ---------------- big-weight / lora_B transpose (tile 32n x 64k) ----
        float (*t)[33] = reinterpret_cast<float(*)[33]>(smraw);
        int which = bid / 28672;
        int b     = bid % 28672;
        const float* W;
        __half* out;
        int K, N, nBlk;
        if (which == 0)      { W = w1;     out = b1;    K = HDIM; N = FDIM; nBlk = FDIM / 32; }
        else if (which == 1) { W = w3;     out = b3;    K = HDIM; N = FDIM; nBlk = FDIM / 32; }
        else if (which == 2) { W = w2;     out = b2;    K = FDIM; N = HDIM; nBlk = HDIM / 32; }
        else                 { W = lora_B; out = g_lbT; K = 64;   N = HDIM; nBlk = HDIM / 32; }

        int n0 = (b % nBlk) * 32;
        int k0 = (b / nBlk) * 64;

        {
            int row = tid >> 3;
            int c4  = (tid & 7) * 4;
            #pragma unroll
            for (int rr = 0; rr < 64; rr += 32) {
                float4 v = *(const float4*)(W + (size_t)(k0 + row + rr) * N + n0 + c4);
                t[row + rr][c4 + 0] = v.x;
                t[row + rr][c4 + 1] = v.y;
                t[row + rr][c4 + 2] = v.z;
                t[row + rr][c4 + 3] = v.w;
            }
        }
        __syncthreads();
        {
            int n = tid >> 3;
            int c = tid & 7;
            __half hv[8];
            #pragma unroll
            for (int j = 0; j < 8; j++)
                hv[j] = __float2half_rn(t[8 * c + j][n]);
            *(uint4*)(out + (size_t)(n0 + n) * K + k0 + 8 * c) = *(uint4*)hv;
        }
        return;
    }

    if (bid < TRL_BLOCKS) {
        // ---------------- lora_A transpose: [E,H,R] -> laT [64,H] ----------
        // row n = e*8+r in 0..63, col k = h. 128 blocks: tile 32n x 64k.
        int b  = bid - (TR_BLOCKS + 128);
        int n0 = (b & 1) * 32;
        int k0 = (b >> 1) * 64;
        int nl = tid >> 3;          // 0..31
        int kl = (tid & 7) * 8;     // 0..56
        int n  = n0 + nl;
        int e  = n >> 3, r = n & 7;
        __half hv[8];
        #pragma unroll
        for (int j = 0; j < 8; j++)
            hv[j] = __float2half_rn(
                lora_A[(size_t)e * HDIM * NR + (size_t)(k0 + kl + j) * NR + r]);
        *(uint4*)(g_laT + (size_t)n * HDIM + k0 + kl) = *(uint4*)hv;
        return;
    }

    // ---------------- router path (256 threads) ----------------
    int n = bid - TRL_BLOCKS;
    float* xs     = (float*)smraw;
    float* logits = (float*)(smraw + HDIM * 4);
    int*   sel    = (int*)(logits + NEXP);
    float* rws    = (float*)(sel + 2);

    const float* xr = x + (size_t)n * HDIM;
    for (int i = tid; i < HDIM / 4; i += 256)
        ((float4*)xs)[i] = ((const float4*)xr)[i];
    __syncthreads();

    // fp16 conversion of x
    {
        __half* xo = g_xh + (size_t)n * HDIM;
        for (int i = tid; i < HDIM / 2; i += 256)
            *(__half2*)(xo + 2 * i) = __floats2half2_rn(xs[2 * i], xs[2 * i + 1]);
    }

    int wid = tid >> 5, lane = tid & 31;
    // logits: one expert per warp
    {
        int e = wid;
        const float* wr = router_w + (size_t)e * HDIM;
        float s = 0.f;
        for (int h = lane; h < HDIM; h += 32) s += xs[h] * wr[h];
        #pragma unroll
        for (int o = 16; o; o >>= 1) s += __shfl_down_sync(0xffffffffu, s, o);
        if (lane == 0) {
            logits[e] = s;
            if (logits_out) logits_out[(size_t)n * NEXP + e] = s;
        }
    }
    __syncthreads();

    if (tid == 0) {
        float m = -1e30f;
        for (int e = 0; e < NEXP; e++) m = fmaxf(m, logits[e]);
        float p[NEXP];
        for (int e = 0; e < NEXP; e++) p[e] = expf(logits[e] - m);
        int i0 = 0;
        for (int e = 1; e < NEXP; e++) if (p[e] > p[i0]) i0 = e;
        int i1 = -1;
        for (int e = 0; e < NEXP; e++) {
            if (e == i0) continue;
            if (i1 < 0 || p[e] > p[i1]) i1 = e;
        }
        float s2 = p[i0] + p[i1];
        sel[0] = i0; sel[1] = i1;
        rws[0] = p[i0] / s2; rws[1] = p[i1] / s2;
    }
    __syncthreads();

    // masked routing weights (LSCALE folded in)
    if (tid < NEXP) {
        float v = 0.f;
        if (tid == sel[0]) v = rws[0] * LSCALE;
        else if (tid == sel[1]) v = rws[1] * LSCALE;
        g_rw8[n * NEXP + tid] = v;
    }
}

// ---------------------------------------------------------------------------
// FUSED gate+up GEMM, 128m x 64n CTA tile (occ=2), + 32 tail LoRA-A tiles.
// Grid (FDIM/64 + 1, NTOK/128) = (225, 32). lin >= 7168 => LoRA tile:
//   same mainloop with B1 = B3 = laT (n0 = 0), epilogue writes
//   c16[m][c] = fp16(accG[c] * rw8[m][c>>3]).
// ---------------------------------------------------------------------------
#define FSTG 32768
#define FUSED_SMEM (3 * FSTG)
#define GU_MAIN (224 * 32)

__device__ __forceinline__ void issue_stage_gu(
    uint32_t st, const __half* A, const __half* B1, const __half* B3,
    int m0, int n0, int kpos, int K, int lr, int lkc)
{
    #pragma unroll
    for (int rr = 0; rr < 256; rr += 32) {
        int row = lr + rr;
        uint32_t so = row * 128 + ((lkc ^ (row & 7)) << 4);
        const __half* src;
        if (rr < 128)      src = A  + (size_t)(m0 + row) * K;
        else if (rr < 192) src = B1 + (size_t)(n0 + row - 128) * K;
        else               src = B3 + (size_t)(n0 + row - 192) * K;
        CP16(st + so, src + kpos + lkc * 8);
    }
    CP_COMMIT();
}

__global__ void __launch_bounds__(256, 2) gemm_gateup_kernel(
    const __half* __restrict__ A, const __half* __restrict__ B1,
    const __half* __restrict__ B3, __half* __restrict__ oA2,
    const __half* __restrict__ laT, __half* __restrict__ oC16,
    const float* __restrict__ rw8, int K)
{
    extern __shared__ __align__(1024) char smem[];
    uint32_t sb = smem_u32(smem);
    int tid = threadIdx.x;
    int wid = tid >> 5, lane = tid & 31;
    int wm = wid >> 2, wn = wid & 3;

    int lin = blockIdx.y * gridDim.x + blockIdx.x;
    bool loraTile = (lin >= GU_MAIN);
    int m0, n0;
    const __half* Bp1;
    const __half* Bp3;
    if (loraTile) {
        m0 = (lin - GU_MAIN) * 128;
        n0 = 0;
        Bp1 = laT; Bp3 = laT;
    } else {
        int gs = 8 * 32;
        int g  = lin / gs, r = lin - g * gs;
        m0 = (r >> 3) * 128;
        n0 = (g * 8 + (r & 7)) * 64;
        Bp1 = B1; Bp3 = B3;
    }

    int NT = K >> 6;
    int lr = tid >> 3, lkc = tid & 7;

    int laneM  = lane & 15;
    int kHalfA = lane >> 4;
    int aSw    = laneM & 7;
    uint32_t rowOffA[4];
    #pragma unroll
    for (int tm = 0; tm < 4; tm++)
        rowOffA[tm] = (uint32_t)(wm * 64 + tm * 16 + laneM) * 128;
    int l7     = lane & 7;
    int kHalfB = (lane >> 3) & 1;
    uint32_t rowB = (uint32_t)(wn * 16 + ((lane >> 4) & 1) * 8 + l7) * 128;

    float accG[4][2][4], accU[4][2][4];
    #pragma unroll
    for (int i = 0; i < 4; i++)
        #pragma unroll
        for (int j = 0; j < 2; j++)
            #pragma unroll
            for (int q = 0; q < 4; q++) { accG[i][j][q] = 0.f; accU[i][j][q] = 0.f; }

    issue_stage_gu(sb,        A, Bp1, Bp3, m0, n0, 0,  K, lr, lkc);
    issue_stage_gu(sb + FSTG, A, Bp1, Bp3, m0, n0, 64, K, lr, lkc);

    for (int kt = 0; kt < NT; kt++) {
        CP_WAIT1();
        __syncthreads();
        if (kt + 2 < NT)
            issue_stage_gu(sb + ((kt + 2) % 3) * FSTG, A, Bp1, Bp3,
                           m0, n0, (kt + 2) << 6, K, lr, lkc);
        else
            CP_COMMIT();

        uint32_t st = sb + (kt % 3) * FSTG;
        #pragma unroll
        for (int kk = 0; kk < 4; kk++) {
            uint32_t ah[4][4], b1f[4], b3f[4];
            uint32_t chA = (uint32_t)(((kk * 2 + kHalfA) ^ aSw) << 4);
            #pragma unroll
            for (int tm = 0; tm < 4; tm++)
                LDSM4(ah[tm][0], ah[tm][1], ah[tm][2], ah[tm][3], st + rowOffA[tm] + chA);
            uint32_t chB = (uint32_t)(((kk * 2 + kHalfB) ^ l7) << 4);
            LDSM4(b1f[0], b1f[1], b1f[2], b1f[3], st + 16384 + rowB + chB);
            LDSM4(b3f[0], b3f[1], b3f[2], b3f[3], st + 24576 + rowB + chB);
            #pragma unroll
            for (int tm = 0; tm < 4; tm++)
                #pragma unroll
                for (int tn = 0; tn < 2; tn++) {
                    MMA_F16(accG[tm][tn], ah[tm][0], ah[tm][1], ah[tm][2], ah[tm][3],
                            b1f[2 * tn], b1f[2 * tn + 1]);
                    MMA_F16(accU[tm][tn], ah[tm][0], ah[tm][1], ah[tm][2], ah[tm][3],
                            b3f[2 * tn], b3f[2 * tn + 1]);
                }
        }
    }

    int g2 = lane >> 2, q2 = (lane & 3) * 2;
    #pragma unroll
    for (int tm = 0; tm < 4; tm++) {
        #pragma unroll
        for (int tn = 0; tn < 2; tn++) {
            int mg = m0 + wm * 64 + tm * 16 + g2;
            int cg = n0 + wn * 16 + tn * 8 + q2;
            float* gg = accG[tm][tn];
            if (loraTile) {
                // c16[m][c] = accG[c] * rw8[m][c>>3]   (pairs share expert: q2 even)
                float wA = rw8[mg * NEXP + (cg >> 3)];
                float wB = rw8[(mg + 8) * NEXP + (cg >> 3)];
                size_t o0 = (size_t)mg * 64 + cg;
                size_t o1 = o0 + 8 * 64;
                *(__half2*)(oC16 + o0) = __floats2half2_rn(gg[0] * wA, gg[1] * wA);
                *(__half2*)(oC16 + o1) = __floats2half2_rn(gg[2] * wB, gg[3] * wB);
            } else {
                float* uu = accU[tm][tn];
                size_t o0 = (size_t)mg * FDIM + cg;
                size_t o1 = o0 + (size_t)8 * FDIM;
                float v0 = gg[0] / (1.f + __expf(-gg[0])) * uu[0];
                float v1 = gg[1] / (1.f + __expf(-gg[1])) * uu[1];
                float v2 = gg[2] / (1.f + __expf(-gg[2])) * uu[2];
                float v3 = gg[3] / (1.f + __expf(-gg[3])) * uu[3];
                *(__half2*)(oA2 + o0) = __floats2half2_rn(v0, v1);
                *(__half2*)(oA2 + o1) = __floats2half2_rn(v2, v3);
            }
        }
    }
}

// ---------------------------------------------------------------------------
// Down-projection + LoRA fp16 GEMM (writes out, beta=0). (unchanged)
// ---------------------------------------------------------------------------
#define STAGE_BYTES 32768
#define GEMM_SMEM   (3 * STAGE_BYTES)

__device__ __forceinline__ void issue_stage_dn(
    uint32_t st, const __half* A, const __half* B,
    const __half* cA, const __half* cB,
    int m0, int n0, int ci, int K, int lr, int lkc)
{
    #pragma unroll
    for (int rr = 0; rr < 128; rr += 32) {
        int row = lr + rr;
        uint32_t so = row * 128 + ((lkc ^ (row & 7)) << 4);
        const __half* sA;
        const __half* sB;
        if (ci == 0) {
            sA = cA + (size_t)(m0 + row) * 64 + lkc * 8;
            sB = cB + (size_t)(n0 + row) * 64 + lkc * 8;
        } else {
            int kpos = (ci - 1) << 6;
            sA = A + (size_t)(m0 + row) * K + kpos + lkc * 8;
            sB = B + (size_t)(n0 + row) * K + kpos + lkc * 8;
        }
        CP16(st + so,         sA);
        CP16(st + 16384 + so, sB);
    }
    CP_COMMIT();
}

__global__ void __launch_bounds__(256, 2) gemm_down_kernel(
    const __half* __restrict__ A, const __half* __restrict__ B,
    const __half* __restrict__ cA, const __half* __restrict__ cB,
    float* __restrict__ C, int K)
{
    extern __shared__ __align__(1024) char smem[];
    uint32_t sb = smem_u32(smem);
    int tid = threadIdx.x;
    int wid = tid >> 5, lane = tid & 31;
    int wm = wid >> 2, wn = wid & 3;

    int lin = blockIdx.y * gridDim.x + blockIdx.x;
    int gs  = 8 * gridDim.y;
    int g   = lin / gs, r = lin - g * gs;
    int m0  = (r >> 3) * 128;
    int n0  = (g * 8 + (r & 7)) * 128;

    int NCH = (K >> 6) + 1;
    int lr = tid >> 3, lkc = tid & 7;

    int laneM  = lane & 15;
    int kHalfA = lane >> 4;
    int aSw    = laneM & 7;
    uint32_t rowOffA[4];
    #pragma unroll
    for (int tm = 0; tm < 4; tm++)
        rowOffA[tm] = (uint32_t)(wm * 64 + tm * 16 + laneM) * 128;
    int l7     = lane & 7;
    int kHalfB = (lane >> 3) & 1;
    uint32_t rowOffB[2];
    #pragma unroll
    for (int pr = 0; pr < 2; pr++)
        rowOffB[pr] = (uint32_t)(wn * 32 + pr * 16 + ((lane >> 4) & 1) * 8 + l7) * 128;

    float acc[4][4][4];
    #pragma unroll
    for (int i = 0; i < 4; i++)
        #pragma unroll
        for (int j = 0; j < 4; j++)
            #pragma unroll
            for (int q = 0; q < 4; q++) acc[i][j][q] = 0.f;

    issue_stage_dn(sb,               A, B, cA, cB, m0, n0, 0, K, lr, lkc);
    issue_stage_dn(sb + STAGE_BYTES, A, B, cA, cB, m0, n0, 1, K, lr, lkc);

    for (int ci = 0; ci < NCH; ci++) {
        CP_WAIT1();
        __syncthreads();
        if (ci + 2 < NCH)
            issue_stage_dn(sb + ((ci + 2) % 3) * STAGE_BYTES, A, B, cA, cB,
                           m0, n0, ci + 2, K, lr, lkc);
        else
            CP_COMMIT();

        uint32_t st = sb + (ci % 3) * STAGE_BYTES;
        #pragma unroll
        for (int kk = 0; kk < 4; kk++) {
            uint32_t ah[4][4], bh[8];
            uint32_t chA = (uint32_t)(((kk * 2 + kHalfA) ^ aSw) << 4);
            #pragma unroll
            for (int tm = 0; tm < 4; tm++)
                LDSM4(ah[tm][0], ah[tm][1], ah[tm][2], ah[tm][3], st + rowOffA[tm] + chA);
            uint32_t chB = (uint32_t)(((kk * 2 + kHalfB) ^ l7) << 4);
            LDSM4(bh[0], bh[1], bh[2], bh[3], st + 16384 + rowOffB[0] + chB);
            LDSM4(bh[4], bh[5], bh[6], bh[7], st + 16384 + rowOffB[1] + chB);
            #pragma unroll
            for (int tm = 0; tm < 4; tm++)
                #pragma unroll
                for (int tn = 0; tn < 4; tn++)
                    MMA_F16(acc[tm][tn], ah[tm][0], ah[tm][1], ah[tm][2], ah[tm][3],
                            bh[2 * tn], bh[2 * tn + 1]);
        }
    }

    int g2 = lane >> 2, q2 = (lane & 3) * 2;
    size_t Nt = (size_t)gridDim.x * 128;
    #pragma unroll
    for (int tm = 0; tm < 4; tm++) {
        #pragma unroll
        for (int tn = 0; tn < 4; tn++) {
            int mg = m0 + wm * 64 + tm * 16 + g2;
            int cg = n0 + wn * 32 + tn * 8 + q2;
            size_t o0 = (size_t)mg * Nt + cg;
            size_t o1 = o0 + 8 * Nt;
            float* a = acc[tm][tn];
            *(float2*)(C + o0) = make_float2(a[0], a[1]);
            *(float2*)(C + o1) = make_float2(a[2], a[3]);
        }
    }
}

// ---------------------------------------------------------------------------
extern "C" void kernel_launch(void* const* d_in, const int* in_sizes, int n_in,
                              void* d_out, int out_size)
{
    const float* x        = (const float*)d_in[0];
    const float* router_w = (const float*)d_in[1];
    const float* w1       = (const float*)d_in[2];
    const float* w2       = (const float*)d_in[3];
    const float* w3       = (const float*)d_in[4];
    const float* lora_A   = (const float*)d_in[5];
    const float* lora_B   = (const float*)d_in[6];
    float* out = (float*)d_out;

    static bool init_done = false;
    static __half *xh, *b1, *b3, *b2, *a2, *c16, *lbT, *laT;
    static float *rw8;
    if (!init_done) {
        cudaGetSymbolAddress((void**)&xh,  g_xh);
        cudaGetSymbolAddress((void**)&b1,  g_b1);
        cudaGetSymbolAddress((void**)&b3,  g_b3);
        cudaGetSymbolAddress((void**)&b2,  g_b2);
        cudaGetSymbolAddress((void**)&a2,  g_a2);
        cudaGetSymbolAddress((void**)&c16, g_c16);
        cudaGetSymbolAddress((void**)&lbT, g_lbT);
        cudaGetSymbolAddress((void**)&laT, g_laT);
        cudaGetSymbolAddress((void**)&rw8, g_rw8);
        cudaFuncSetAttribute(gemm_gateup_kernel,
                             cudaFuncAttributeMaxDynamicSharedMemorySize, FUSED_SMEM);
        cudaFuncSetAttribute(gemm_down_kernel,
                             cudaFuncAttributeMaxDynamicSharedMemorySize, GEMM_SMEM);
        init_done = true;
    }

    float* logits_out = nullptr;
    if ((size_t)out_size >= (size_t)NTOK * HDIM + (size_t)NTOK * NEXP)
        logits_out = out + (size_t)NTOK * HDIM;

    // merged prep: transposes (w1,w3,w2,lora_B,lora_A) + router/x-convert
    prep_kernel<<<TRL_BLOCKS + NTOK, 256>>>(
        x, router_w, lora_A, lora_B, logits_out, w1, w3, w2, b1, b3, b2);

    // Fused gate+up (+32 tail LoRA-A tiles): a2 and c16
    gemm_gateup_kernel<<<dim3(FDIM / 64 + 1, NTOK / 128), 256, FUSED_SMEM>>>(
        xh, b1, b3, a2, laT, c16, rw8, HDIM);

    // Down-proj + LoRA prefix: out = c16@lbT^T + a2@w2 (beta=0 store)
    gemm_down_kernel<<<dim3(HDIM / 128, NTOK / 128), 256, GEMM_SMEM>>>(
        a2, b2, c16, lbT, out, FDIM);
}